// round 8
// baseline (speedup 1.0000x reference)
#include <cuda_runtime.h>
#include <cstdint>
#include <math.h>

// Problem constants
#define B_    4
#define NTOK  1032
#define C_    1024
#define H_    16
#define HD    64
#define BH    64            // B_*H_
#define M_ALL 4128          // B_*NTOK
#define SCALE 0.125f        // HD^-0.5
#define W_SOFT 0.8f         // TAU*(1-LAMBDA)
#define W_RCS  1.2f         // TAU*LAMBDA

#define LDA 20              // kv/proj smem row stride (words): 16 + 4 pad
#define NSTG 4              // pipeline stages
#define STG_WORDS (128 * LDA)            // one operand tile, words
#define GEMM_SMEM_WORDS (2 * NSTG * STG_WORDS)  // 20480 words = 81920 B

// Fused-attention smem layout (32-bit words)
#define LDK 68
#define LDV 72
#define LDR 68
#define A_KN (128 * LDK)            // 8704
#define A_VS (A_KN + 64 * LDK)      // 13056
#define A_RB (A_VS + 64 * LDV)      // 17664
#define ATT_WORDS (A_RB + 128 * LDR)// 26368 words = 105472 bytes

// Scratch — K/V/O stored as tf32 bit patterns (pre-converted)
__device__ unsigned g_K[BH * NTOK * HD];
__device__ unsigned g_V[BH * NTOK * HD];
__device__ unsigned g_O[(size_t)M_ALL * C_];

__device__ __forceinline__ unsigned f2tf(float f) {
    unsigned u; asm("cvt.rna.tf32.f32 %0, %1;" : "=r"(u) : "f"(f)); return u;
}
__device__ __forceinline__ void mma_tf32(float* c, unsigned a0, unsigned a1,
                                         unsigned a2, unsigned a3,
                                         unsigned b0, unsigned b1) {
    asm volatile(
        "mma.sync.aligned.m16n8k8.row.col.f32.tf32.tf32.f32 "
        "{%0,%1,%2,%3},{%4,%5,%6,%7},{%8,%9},{%0,%1,%2,%3};"
        : "+f"(c[0]), "+f"(c[1]), "+f"(c[2]), "+f"(c[3])
        : "r"(a0), "r"(a1), "r"(a2), "r"(a3), "r"(b0), "r"(b1));
}
__device__ __forceinline__ void cpasync16(uint32_t dst, const void* src, int sbytes) {
    asm volatile("cp.async.cg.shared.global [%0], [%1], 16, %2;"
                 :: "r"(dst), "l"(src), "r"(sbytes));
}

// ---------------------------------------------------------------------------
// Kernel 1: K,V projection. 4-stage cp.async pipeline, tf32 mma.
// BM=128 BN=128 BK=16, 8 warps 2x4, epilogue stores tf32 bits to g_K/g_V.
// ---------------------------------------------------------------------------
__global__ __launch_bounds__(256) void kv_proj_kernel(
    const float* __restrict__ x, const float* __restrict__ qkv_w,
    const float* __restrict__ qkv_b)
{
    extern __shared__ float smf[];
    float* Asm = smf;                       // [NSTG][128*LDA]
    float* Bsm = smf + NSTG * STG_WORDS;    // [NSTG][128*LDA]
    const int tid = threadIdx.x;
    const int m0 = blockIdx.y * 128, j0 = blockIdx.x * 128;
    const int wid = tid >> 5, lane = tid & 31;
    const int g = lane >> 2, t = lane & 3;
    const int wm = (wid >> 2) * 64, wn = (wid & 3) * 32;
    const int lrow = tid >> 1, lcol = (tid & 1) * 8;
    const float* Wk = qkv_w + (size_t)C_ * C_;

    const int aok = (m0 + lrow < M_ALL) ? 16 : 0;
    const float* ax = x + (size_t)((m0 + lrow < M_ALL) ? (m0 + lrow) : 0) * C_ + lcol;
    const float* bx = Wk + (size_t)(j0 + lrow) * C_ + lcol;
    const uint32_t abase = (uint32_t)__cvta_generic_to_shared(Asm) + (lrow * LDA + lcol) * 4;
    const uint32_t bbase = (uint32_t)__cvta_generic_to_shared(Bsm) + (lrow * LDA + lcol) * 4;
    const uint32_t stgB = STG_WORDS * 4;

#define KV_PREF(kt) do { \
    int s_ = (kt) & (NSTG - 1); \
    cpasync16(abase + s_ * stgB,      ax + (kt) * 16,     aok); \
    cpasync16(abase + s_ * stgB + 16, ax + (kt) * 16 + 4, aok); \
    cpasync16(bbase + s_ * stgB,      bx + (kt) * 16,     16); \
    cpasync16(bbase + s_ * stgB + 16, bx + (kt) * 16 + 4, 16); \
    asm volatile("cp.async.commit_group;"); } while (0)

    float acc[4][4][4];
#pragma unroll
    for (int a = 0; a < 4; a++)
#pragma unroll
        for (int b = 0; b < 4; b++)
#pragma unroll
            for (int c = 0; c < 4; c++) acc[a][b][c] = 0.f;

    KV_PREF(0); KV_PREF(1); KV_PREF(2);

    for (int kt = 0; kt < 64; kt++) {
        asm volatile("cp.async.wait_group %0;" :: "n"(NSTG - 2));
        __syncthreads();
        if (kt + 3 < 64) KV_PREF(kt + 3);

        const float* Af = Asm + (kt & (NSTG - 1)) * STG_WORDS;
        const float* Bf = Bsm + (kt & (NSTG - 1)) * STG_WORDS;
#pragma unroll
        for (int ks = 0; ks < 16; ks += 8) {
            unsigned af[4][4], bf[4][2];
#pragma unroll
            for (int mt = 0; mt < 4; mt++) {
                const float* ap = Af + (wm + mt * 16 + g) * LDA + ks + t;
                af[mt][0] = f2tf(ap[0]);        af[mt][1] = f2tf(ap[8 * LDA]);
                af[mt][2] = f2tf(ap[4]);        af[mt][3] = f2tf(ap[8 * LDA + 4]);
            }
#pragma unroll
            for (int nt = 0; nt < 4; nt++) {
                const float* bp = Bf + (wn + nt * 8 + g) * LDA + ks + t;
                bf[nt][0] = f2tf(bp[0]);        bf[nt][1] = f2tf(bp[4]);
            }
#pragma unroll
            for (int mt = 0; mt < 4; mt++)
#pragma unroll
                for (int nt = 0; nt < 4; nt++)
                    mma_tf32(acc[mt][nt], af[mt][0], af[mt][1], af[mt][2], af[mt][3],
                             bf[nt][0], bf[nt][1]);
        }
    }
#undef KV_PREF

#pragma unroll
    for (int mt = 0; mt < 4; mt++) {
#pragma unroll
        for (int h = 0; h < 2; h++) {
            int m = m0 + wm + mt * 16 + g + h * 8;
            if (m >= M_ALL) continue;
            int b = m / NTOK, n = m - b * NTOK;
#pragma unroll
            for (int nt = 0; nt < 4; nt++) {
                int j = j0 + wn + nt * 8 + t * 2;
#pragma unroll
                for (int c = 0; c < 2; c++) {
                    int jj = j + c;
                    unsigned uv = f2tf(acc[mt][nt][h * 2 + c] + qkv_b[C_ + jj]);
                    if (jj < C_) {
                        int hh = jj >> 6, d = jj & 63;
                        g_K[(((size_t)b * H_ + hh) * NTOK + n) * HD + d] = uv;
                    } else {
                        int j2 = jj - C_;
                        int hh = j2 >> 6, d = j2 & 63;
                        g_V[(((size_t)b * H_ + hh) * NTOK + n) * HD + d] = uv;
                    }
                }
            }
        }
    }
}

// ---------------------------------------------------------------------------
// Kernel 2: fused attention. Block = (bh, 128 m-rows), n-tile 64, 17 iters.
// 103 KB smem -> 2 CTAs/SM. K/V tiles arrive as tf32 bits (no cvt in GEMMs).
// ---------------------------------------------------------------------------
__global__ __launch_bounds__(256, 2) void attn_fused_kernel(
    const float* __restrict__ addn, const float* __restrict__ rcs)
{
    extern __shared__ unsigned smu[];
    unsigned* Km = smu;
    unsigned* Kn = smu + A_KN;
    unsigned* Vs = smu + A_VS;
    float*    Rb = (float*)(smu + A_RB);
    const int tid = threadIdx.x;
    const int bh = blockIdx.y;
    const int b = bh >> 4, hh = bh & 15;
    const int m0 = blockIdx.x * 128;
    const int wid = tid >> 5, lane = tid & 31;
    const int g = lane >> 2, t = lane & 3;
    const int r0 = wid * 16 + g;
    const int r1 = r0 + 8;
    const int gm0 = m0 + r0, gm1 = m0 + r1;
    const unsigned* Kbh = g_K + (size_t)bh * NTOK * HD;
    const unsigned* Vbh = g_V + (size_t)bh * NTOK * HD;
    const float* Rbh = rcs + (size_t)bh * NTOK * NTOK;
    const float* ad0p = addn + (size_t)(gm0 < NTOK ? gm0 : 0) * NTOK;
    const float* ad1p = addn + (size_t)(gm1 < NTOK ? gm1 : 0) * NTOK;

    const uint32_t su = (uint32_t)__cvta_generic_to_shared(smu);

    // Km fill (128 x 64 tf32 words)
#pragma unroll
    for (int i = 0; i < 8; i++) {
        int c = tid + i * 256;
        int row = c >> 4, ch = (c & 15) * 4;
        uint4 v = make_uint4(0u, 0u, 0u, 0u);
        if (m0 + row < NTOK)
            v = *(const uint4*)(Kbh + (size_t)(m0 + row) * HD + ch);
        *(uint4*)(Km + row * LDK + ch) = v;
    }

    float accS[8][4];
    float accP[8][4], accR[8][4];
#pragma unroll
    for (int nt = 0; nt < 8; nt++)
#pragma unroll
        for (int q = 0; q < 4; q++) { accP[nt][q] = 0.f; accR[nt][q] = 0.f; }
    float rs0 = 0.f, rs1 = 0.f;

    for (int it = 0; it < 17; it++) {
        const int n0 = it * 64;
        __syncthreads();  // smem reuse barrier; Km visible on it=0

        // group 0: Kn + Vs (64 rows each)
#pragma unroll
        for (int i = 0; i < 4; i++) {
            int c = tid + i * 256;
            int row = c >> 4, ch = (c & 15) * 4;
            int tok = n0 + row;
            int ok = (tok < NTOK);
            cpasync16(su + (A_KN + row * LDK + ch) * 4,
                      Kbh + (size_t)(ok ? tok : 0) * HD + ch, ok ? 16 : 0);
        }
#pragma unroll
        for (int i = 0; i < 4; i++) {
            int c = tid + i * 256;
            int row = c >> 4, ch = (c & 15) * 4;
            int tok = n0 + row;
            int ok = (tok < NTOK);
            cpasync16(su + (A_VS + row * LDV + ch) * 4,
                      Vbh + (size_t)(ok ? tok : 0) * HD + ch, ok ? 16 : 0);
        }
        asm volatile("cp.async.commit_group;");

        // group 1: rcs tile (128 x 64 fp32)
#pragma unroll
        for (int i = 0; i < 8; i++) {
            int c = tid + i * 256;
            int row = c >> 4, ch = (c & 15) * 4;
            int mm = m0 + row, nn = n0 + ch;
            int ok = (mm < NTOK) && (nn < NTOK);
            cpasync16(su + (A_RB + row * LDR + ch) * 4,
                      Rbh + (size_t)(ok ? mm : 0) * NTOK + (ok ? nn : 0), ok ? 16 : 0);
        }
        asm volatile("cp.async.commit_group;");

        asm volatile("cp.async.wait_group 1;");
        __syncthreads();

        // ---- GEMM1: accS(16x64) = Km . Kn^T ----
#pragma unroll
        for (int nt = 0; nt < 8; nt++)
#pragma unroll
            for (int q = 0; q < 4; q++) accS[nt][q] = 0.f;

#pragma unroll
        for (int ks = 0; ks < 8; ks++) {
            unsigned a0 = Km[r0 * LDK + ks * 8 + t];
            unsigned a1 = Km[r1 * LDK + ks * 8 + t];
            unsigned a2 = Km[r0 * LDK + ks * 8 + t + 4];
            unsigned a3 = Km[r1 * LDK + ks * 8 + t + 4];
#pragma unroll
            for (int nt = 0; nt < 8; nt++) {
                unsigned b0 = Kn[(nt * 8 + g) * LDK + ks * 8 + t];
                unsigned b1 = Kn[(nt * 8 + g) * LDK + ks * 8 + t + 4];
                mma_tf32(accS[nt], a0, a1, a2, a3, b0, b1);
            }
        }

        // ---- exp epilogue + rowsum partials ----
#pragma unroll
        for (int nt = 0; nt < 8; nt++) {
            int n = n0 + nt * 8 + 2 * t;
            if (n < NTOK) {
                float e0 = 0.f, e1 = 0.f, e2 = 0.f, e3 = 0.f;
                if (gm0 < NTOK) {
                    float2 a = *(const float2*)(ad0p + n);
                    e0 = __expf(SCALE * accS[nt][0] + a.x);
                    e1 = __expf(SCALE * accS[nt][1] + a.y);
                }
                if (gm1 < NTOK) {
                    float2 a = *(const float2*)(ad1p + n);
                    e2 = __expf(SCALE * accS[nt][2] + a.x);
                    e3 = __expf(SCALE * accS[nt][3] + a.y);
                }
                accS[nt][0] = e0; accS[nt][1] = e1;
                accS[nt][2] = e2; accS[nt][3] = e3;
                rs0 += e0 + e1; rs1 += e2 + e3;
            } else {
                accS[nt][0] = 0.f; accS[nt][1] = 0.f;
                accS[nt][2] = 0.f; accS[nt][3] = 0.f;
            }
        }

        asm volatile("cp.async.wait_group 0;");
        __syncthreads();

        // ---- fused GEMM2 (P@V) + GEMM3 (rcs@V) ----
        const int srcA = (lane & 28) | (t >> 1);
        const int srcB = srcA + 2;
        const bool odd = (t & 1);
#pragma unroll
        for (int ks = 0; ks < 8; ks++) {
            float c0 = accS[ks][0], c1 = accS[ks][1];
            float c2 = accS[ks][2], c3 = accS[ks][3];
            float x0 = __shfl_sync(0xffffffffu, c0, srcA);
            float x1 = __shfl_sync(0xffffffffu, c1, srcA);
            float y0 = __shfl_sync(0xffffffffu, c0, srcB);
            float y1 = __shfl_sync(0xffffffffu, c1, srcB);
            float w0 = __shfl_sync(0xffffffffu, c2, srcA);
            float w1 = __shfl_sync(0xffffffffu, c3, srcA);
            float u0 = __shfl_sync(0xffffffffu, c2, srcB);
            float u1 = __shfl_sync(0xffffffffu, c3, srcB);
            unsigned pa0 = f2tf(odd ? x1 : x0);
            unsigned pa1 = f2tf(odd ? w1 : w0);
            unsigned pa2 = f2tf(odd ? y1 : y0);
            unsigned pa3 = f2tf(odd ? u1 : u0);
            unsigned ra0 = f2tf(Rb[r0 * LDR + ks * 8 + t]);
            unsigned ra1 = f2tf(Rb[r1 * LDR + ks * 8 + t]);
            unsigned ra2 = f2tf(Rb[r0 * LDR + ks * 8 + t + 4]);
            unsigned ra3 = f2tf(Rb[r1 * LDR + ks * 8 + t + 4]);
#pragma unroll
            for (int nt = 0; nt < 8; nt++) {
                unsigned b0 = Vs[(ks * 8 + t) * LDV + nt * 8 + g];
                unsigned b1 = Vs[(ks * 8 + t + 4) * LDV + nt * 8 + g];
                mma_tf32(accP[nt], pa0, pa1, pa2, pa3, b0, b1);
                mma_tf32(accR[nt], ra0, ra1, ra2, ra3, b0, b1);
            }
        }
    }

    // ---- final epilogue: normalize + mix + store tf32 bits to g_O ----
    rs0 += __shfl_xor_sync(0xffffffffu, rs0, 1);
    rs0 += __shfl_xor_sync(0xffffffffu, rs0, 2);
    rs1 += __shfl_xor_sync(0xffffffffu, rs1, 1);
    rs1 += __shfl_xor_sync(0xffffffffu, rs1, 2);
    const float inv0 = W_SOFT / rs0, inv1 = W_SOFT / rs1;

    if (gm0 < NTOK) {
        unsigned* op = g_O + ((size_t)b * NTOK + gm0) * C_ + hh * HD;
#pragma unroll
        for (int nt = 0; nt < 8; nt++) {
            int d = nt * 8 + 2 * t;
            uint2 v;
            v.x = f2tf(accP[nt][0] * inv0 + W_RCS * accR[nt][0]);
            v.y = f2tf(accP[nt][1] * inv0 + W_RCS * accR[nt][1]);
            *(uint2*)(op + d) = v;
        }
    }
    if (gm1 < NTOK) {
        unsigned* op = g_O + ((size_t)b * NTOK + gm1) * C_ + hh * HD;
#pragma unroll
        for (int nt = 0; nt < 8; nt++) {
            int d = nt * 8 + 2 * t;
            uint2 v;
            v.x = f2tf(accP[nt][2] * inv1 + W_RCS * accR[nt][2]);
            v.y = f2tf(accP[nt][3] * inv1 + W_RCS * accR[nt][3]);
            *(uint2*)(op + d) = v;
        }
    }
}

// ---------------------------------------------------------------------------
// Kernel 3: out = g_O @ proj_w^T + proj_b. 4-stage cp.async, tf32 mma.
// A operand (g_O) already tf32 bits — no cvt.
// ---------------------------------------------------------------------------
__global__ __launch_bounds__(256) void proj_kernel(
    const float* __restrict__ proj_w, const float* __restrict__ proj_b,
    float* __restrict__ out)
{
    extern __shared__ unsigned smp[];
    unsigned* Asm = smp;                      // [NSTG][128*LDA] tf32 bits
    float*    Bsm = (float*)(smp + NSTG * STG_WORDS);
    const int tid = threadIdx.x;
    const int m0 = blockIdx.y * 128, j0 = blockIdx.x * 128;
    const int wid = tid >> 5, lane = tid & 31;
    const int g = lane >> 2, t = lane & 3;
    const int wm = (wid >> 2) * 64, wn = (wid & 3) * 32;
    const int lrow = tid >> 1, lcol = (tid & 1) * 8;

    const int aok = (m0 + lrow < M_ALL) ? 16 : 0;
    const unsigned* ax = g_O + (size_t)((m0 + lrow < M_ALL) ? (m0 + lrow) : 0) * C_ + lcol;
    const float* bx = proj_w + (size_t)(j0 + lrow) * C_ + lcol;
    const uint32_t abase = (uint32_t)__cvta_generic_to_shared(Asm) + (lrow * LDA + lcol) * 4;
    const uint32_t bbase = (uint32_t)__cvta_generic_to_shared(Bsm) + (lrow * LDA + lcol) * 4;
    const uint32_t stgB = STG_WORDS * 4;

#define PJ_PREF(kt) do { \
    int s_ = (kt) & (NSTG - 1); \
    cpasync16(abase + s_ * stgB,      ax + (kt) * 16,     aok); \
    cpasync16(abase + s_ * stgB + 16, ax + (kt) * 16 + 4, aok); \
    cpasync16(bbase + s_ * stgB,      bx + (kt) * 16,     16); \
    cpasync16(bbase + s_ * stgB + 16, bx + (kt) * 16 + 4, 16); \
    asm volatile("cp.async.commit_group;"); } while (0)

    float acc[4][4][4];
#pragma unroll
    for (int a = 0; a < 4; a++)
#pragma unroll
        for (int b = 0; b < 4; b++)
#pragma unroll
            for (int c = 0; c < 4; c++) acc[a][b][c] = 0.f;

    PJ_PREF(0); PJ_PREF(1); PJ_PREF(2);

    for (int kt = 0; kt < 64; kt++) {
        asm volatile("cp.async.wait_group %0;" :: "n"(NSTG - 2));
        __syncthreads();
        if (kt + 3 < 64) PJ_PREF(kt + 3);

        const unsigned* Au = Asm + (kt & (NSTG - 1)) * STG_WORDS;
        const float* Bf = Bsm + (kt & (NSTG - 1)) * STG_WORDS;
#pragma unroll
        for (int ks = 0; ks < 16; ks += 8) {
            unsigned af[4][4], bf[4][2];
#pragma unroll
            for (int mt = 0; mt < 4; mt++) {
                const unsigned* ap = Au + (wm + mt * 16 + g) * LDA + ks + t;
                af[mt][0] = ap[0];       af[mt][1] = ap[8 * LDA];
                af[mt][2] = ap[4];       af[mt][3] = ap[8 * LDA + 4];
            }
#pragma unroll
            for (int nt = 0; nt < 4; nt++) {
                const float* bp = Bf + (wn + nt * 8 + g) * LDA + ks + t;
                bf[nt][0] = f2tf(bp[0]); bf[nt][1] = f2tf(bp[4]);
            }
#pragma unroll
            for (int mt = 0; mt < 4; mt++)
#pragma unroll
                for (int nt = 0; nt < 4; nt++)
                    mma_tf32(acc[mt][nt], af[mt][0], af[mt][1], af[mt][2], af[mt][3],
                             bf[nt][0], bf[nt][1]);
        }
    }
#undef PJ_PREF

#pragma unroll
    for (int mt = 0; mt < 4; mt++) {
#pragma unroll
        for (int h = 0; h < 2; h++) {
            int m = m0 + wm + mt * 16 + g + h * 8;
            if (m >= M_ALL) continue;
#pragma unroll
            for (int nt = 0; nt < 4; nt++) {
                int j = j0 + wn + nt * 8 + t * 2;
                float2 v = make_float2(acc[mt][nt][h * 2 + 0] + proj_b[j],
                                       acc[mt][nt][h * 2 + 1] + proj_b[j + 1]);
                *(float2*)(out + (size_t)m * C_ + j) = v;
            }
        }
    }
}

// ---------------------------------------------------------------------------
extern "C" void kernel_launch(void* const* d_in, const int* in_sizes, int n_in,
                              void* d_out, int out_size)
{
    const float* x      = (const float*)d_in[0];
    const float* qkv_w  = (const float*)d_in[1];
    const float* qkv_b  = (const float*)d_in[2];
    const float* proj_w = (const float*)d_in[3];
    const float* proj_b = (const float*)d_in[4];
    const float* addn   = (const float*)d_in[5];
    const float* rcs    = (const float*)d_in[6];
    float* out = (float*)d_out;

    cudaFuncSetAttribute(kv_proj_kernel,
                         cudaFuncAttributeMaxDynamicSharedMemorySize,
                         GEMM_SMEM_WORDS * 4);
    cudaFuncSetAttribute(proj_kernel,
                         cudaFuncAttributeMaxDynamicSharedMemorySize,
                         GEMM_SMEM_WORDS * 4);
    cudaFuncSetAttribute(attn_fused_kernel,
                         cudaFuncAttributeMaxDynamicSharedMemorySize,
                         ATT_WORDS * 4);

    kv_proj_kernel<<<dim3(16, 33), 256, GEMM_SMEM_WORDS * 4>>>(x, qkv_w, qkv_b);
    attn_fused_kernel<<<dim3(9, 64), 256, ATT_WORDS * 4>>>(addn, rcs);
    proj_kernel<<<dim3(8, 33), 256, GEMM_SMEM_WORDS * 4>>>(proj_w, proj_b, out);
}

// round 14
// speedup vs baseline: 1.1388x; 1.1388x over previous
#include <cuda_runtime.h>
#include <cuda_fp16.h>
#include <cstdint>
#include <math.h>

// Problem constants
#define B_    4
#define NTOK  1032
#define NTOK2 1088          // padded token stride (zeros in pad)
#define C_    1024
#define H_    16
#define HD    64
#define BH    64            // B_*H_
#define M_ALL 4128          // B_*NTOK
#define SCALE 0.125f
#define W_SOFT 0.8f
#define W_RCS  1.2f

// GEMM smem (fp32 tiles, identical to R8): row = 16 words + 4 pad
#define LDA 20
#define NSTG 4
#define STG_WORDS (128 * LDA)                   // 2560
#define GEMM_SMEM_WORDS (2 * NSTG * STG_WORDS)  // 81920 bytes

// attn smem (words): Km 128x36, Kn 64x36, Vs 64x36, Rb 128x68
#define LDKM 36
#define LDKN 36
#define LDVS 36
#define LDR  68
#define KM_OFF 0
#define KN_OFF (128 * LDKM)             // 4608
#define VS_OFF (KN_OFF + 64 * LDKN)     // 6912
#define RB_OFF (VS_OFF + 64 * LDVS)     // 9216
#define ATT_WORDS (RB_OFF + 128 * LDR)  // 17920 words = 71680 bytes

// Scratch (zero-initialized; total 34.7 MB < R8's 50.7 MB which passed)
__device__ __half g_K[(size_t)BH * NTOK2 * HD];   // [bh][tok(1088)][d]  fp16
__device__ __half g_V[(size_t)BH * HD * NTOK2];   // [bh][d][tok(1088)]  fp16 (transposed)
__device__ float  g_O[(size_t)M_ALL * C_];        // [m][c] fp32

// ---------------------------------------------------------------------------
__device__ __forceinline__ unsigned f16x2(float lo, float hi) {
    unsigned r;
    asm("cvt.rn.f16x2.f32 %0, %1, %2;" : "=r"(r) : "f"(hi), "f"(lo));
    return r;
}
__device__ __forceinline__ void mma_f16(float* c, unsigned a0, unsigned a1,
                                        unsigned a2, unsigned a3,
                                        unsigned b0, unsigned b1) {
    asm volatile(
        "mma.sync.aligned.m16n8k16.row.col.f32.f16.f16.f32 "
        "{%0,%1,%2,%3},{%4,%5,%6,%7},{%8,%9},{%0,%1,%2,%3};"
        : "+f"(c[0]), "+f"(c[1]), "+f"(c[2]), "+f"(c[3])
        : "r"(a0), "r"(a1), "r"(a2), "r"(a3), "r"(b0), "r"(b1));
}
__device__ __forceinline__ void cpasync16(uint32_t dst, const void* src, int sbytes) {
    asm volatile("cp.async.cg.shared.global [%0], [%1], 16, %2;"
                 :: "r"(dst), "l"(src), "r"(sbytes));
}

// ---------------------------------------------------------------------------
// Shared fp16-mma GEMM mainloop over fp32 smem tiles (R8 pipeline verbatim).
// 128x128 tile, K=1024 (64 k16 steps), 256 threads, warps 2x4.
// ---------------------------------------------------------------------------
__device__ __forceinline__ void wg_gemm(
    const float* __restrict__ Arow, const float* __restrict__ Brow, int aok,
    float* smem, float acc[4][4][4], int wm, int wn, int g, int t,
    uint32_t abase, uint32_t bbase)
{
    const uint32_t stgB = STG_WORDS * 4;

#define WG_PREF(kt) do { \
    int s_ = (kt) & (NSTG - 1); \
    cpasync16(abase + s_ * stgB,      Arow + (kt) * 16,     aok); \
    cpasync16(abase + s_ * stgB + 16, Arow + (kt) * 16 + 4, aok); \
    cpasync16(bbase + s_ * stgB,      Brow + (kt) * 16,     16); \
    cpasync16(bbase + s_ * stgB + 16, Brow + (kt) * 16 + 4, 16); \
    asm volatile("cp.async.commit_group;"); } while (0)

    WG_PREF(0); WG_PREF(1); WG_PREF(2);

    for (int kt = 0; kt < 64; kt++) {
        asm volatile("cp.async.wait_group %0;" :: "n"(NSTG - 2));
        __syncthreads();
        if (kt + 3 < 64) WG_PREF(kt + 3);

        const float* Af = smem + (kt & (NSTG - 1)) * STG_WORDS;
        const float* Bf = Af + NSTG * STG_WORDS;

        unsigned a[4][4], bb[4][2];
#pragma unroll
        for (int mt = 0; mt < 4; mt++) {
            const float* ap = Af + (wm + mt * 16 + g) * LDA + 2 * t;
            float2 p0 = *(const float2*)ap;
            float2 p1 = *(const float2*)(ap + 8 * LDA);
            float2 p2 = *(const float2*)(ap + 8);
            float2 p3 = *(const float2*)(ap + 8 * LDA + 8);
            a[mt][0] = f16x2(p0.x, p0.y);
            a[mt][1] = f16x2(p1.x, p1.y);
            a[mt][2] = f16x2(p2.x, p2.y);
            a[mt][3] = f16x2(p3.x, p3.y);
        }
#pragma unroll
        for (int nt = 0; nt < 4; nt++) {
            const float* bp = Bf + (wn + nt * 8 + g) * LDA + 2 * t;
            float2 q0 = *(const float2*)bp;
            float2 q1 = *(const float2*)(bp + 8);
            bb[nt][0] = f16x2(q0.x, q0.y);
            bb[nt][1] = f16x2(q1.x, q1.y);
        }
#pragma unroll
        for (int mt = 0; mt < 4; mt++)
#pragma unroll
            for (int nt = 0; nt < 4; nt++)
                mma_f16(acc[mt][nt], a[mt][0], a[mt][1], a[mt][2], a[mt][3],
                        bb[nt][0], bb[nt][1]);
    }
#undef WG_PREF
}

// ---------------------------------------------------------------------------
// Kernel 1: K,V projection. Grid (16, 33), 256 threads. Writes fp16 K/V.
// ---------------------------------------------------------------------------
__global__ __launch_bounds__(256) void kv_proj_kernel(
    const float* __restrict__ x, const float* __restrict__ qkv_w,
    const float* __restrict__ qkv_b)
{
    extern __shared__ float sm_kv[];
    const int tid = threadIdx.x;
    const int m0 = blockIdx.y * 128, j0 = blockIdx.x * 128;
    const int wid = tid >> 5, lane = tid & 31;
    const int g = lane >> 2, t = lane & 3;
    const int wm = (wid >> 2) * 64, wn = (wid & 3) * 32;
    const int lrow = tid >> 1, lcol = (tid & 1) * 8;
    const float* Wk = qkv_w + (size_t)C_ * C_;

    const int aok = (m0 + lrow < M_ALL) ? 16 : 0;
    const float* Arow = x + (size_t)((m0 + lrow < M_ALL) ? (m0 + lrow) : 0) * C_ + lcol;
    const float* Brow = Wk + (size_t)(j0 + lrow) * C_ + lcol;
    const uint32_t abase = (uint32_t)__cvta_generic_to_shared(sm_kv)
                           + (lrow * LDA + lcol) * 4;
    const uint32_t bbase = abase + NSTG * STG_WORDS * 4;

    float acc[4][4][4];
#pragma unroll
    for (int a = 0; a < 4; a++)
#pragma unroll
        for (int b = 0; b < 4; b++)
#pragma unroll
            for (int c = 0; c < 4; c++) acc[a][b][c] = 0.f;

    wg_gemm(Arow, Brow, aok, sm_kv, acc, wm, wn, g, t, abase, bbase);

#pragma unroll
    for (int mt = 0; mt < 4; mt++) {
#pragma unroll
        for (int h = 0; h < 2; h++) {
            int m = m0 + wm + mt * 16 + g + h * 8;
            if (m >= M_ALL) continue;
            int b = m / NTOK, n = m - b * NTOK;
#pragma unroll
            for (int nt = 0; nt < 4; nt++) {
                int j = j0 + wn + nt * 8 + t * 2;
#pragma unroll
                for (int c = 0; c < 2; c++) {
                    int jj = j + c;
                    float v = acc[mt][nt][h * 2 + c] + qkv_b[C_ + jj];
                    if (jj < C_) {
                        int hh = jj >> 6, d = jj & 63;
                        g_K[(((size_t)b * H_ + hh) * NTOK2 + n) * HD + d] =
                            __float2half_rn(v);
                    } else {
                        int j2 = jj - C_;
                        int hh = j2 >> 6, d = j2 & 63;
                        g_V[(((size_t)b * H_ + hh) * HD + d) * NTOK2 + n] =
                            __float2half_rn(v);
                    }
                }
            }
        }
    }
}

// ---------------------------------------------------------------------------
// Kernel 3: output projection. Grid (8, 33), 256 threads.
// ---------------------------------------------------------------------------
__global__ __launch_bounds__(256) void proj_kernel(
    const float* __restrict__ proj_w, const float* __restrict__ proj_b,
    float* __restrict__ out)
{
    extern __shared__ float sm_pj[];
    const int tid = threadIdx.x;
    const int m0 = blockIdx.y * 128, j0 = blockIdx.x * 128;
    const int wid = tid >> 5, lane = tid & 31;
    const int g = lane >> 2, t = lane & 3;
    const int wm = (wid >> 2) * 64, wn = (wid & 3) * 32;
    const int lrow = tid >> 1, lcol = (tid & 1) * 8;

    const int aok = (m0 + lrow < M_ALL) ? 16 : 0;
    const float* Arow = g_O + (size_t)((m0 + lrow < M_ALL) ? (m0 + lrow) : 0) * C_ + lcol;
    const float* Brow = proj_w + (size_t)(j0 + lrow) * C_ + lcol;
    const uint32_t abase = (uint32_t)__cvta_generic_to_shared(sm_pj)
                           + (lrow * LDA + lcol) * 4;
    const uint32_t bbase = abase + NSTG * STG_WORDS * 4;

    float acc[4][4][4];
#pragma unroll
    for (int a = 0; a < 4; a++)
#pragma unroll
        for (int b = 0; b < 4; b++)
#pragma unroll
            for (int c = 0; c < 4; c++) acc[a][b][c] = 0.f;

    wg_gemm(Arow, Brow, aok, sm_pj, acc, wm, wn, g, t, abase, bbase);

#pragma unroll
    for (int mt = 0; mt < 4; mt++) {
#pragma unroll
        for (int h = 0; h < 2; h++) {
            int m = m0 + wm + mt * 16 + g + h * 8;
            if (m >= M_ALL) continue;
#pragma unroll
            for (int nt = 0; nt < 4; nt++) {
                int j = j0 + wn + nt * 8 + t * 2;
                float2 v = make_float2(acc[mt][nt][h * 2 + 0] + proj_b[j],
                                       acc[mt][nt][h * 2 + 1] + proj_b[j + 1]);
                *(float2*)(out + (size_t)m * C_ + j) = v;
            }
        }
    }
}

// ---------------------------------------------------------------------------
// Kernel 2: fused attention, fp16 mma. Block = (bh, 128 m-rows), n-tile 64.
// S epilogue C-layout == P@V A-layout: no shuffles.
// ---------------------------------------------------------------------------
__global__ __launch_bounds__(256, 2) void attn_fused_kernel(
    const float* __restrict__ addn, const float* __restrict__ rcs)
{
    extern __shared__ unsigned smu[];
    unsigned* Km = smu + KM_OFF;
    unsigned* Kn = smu + KN_OFF;
    unsigned* Vs = smu + VS_OFF;
    float*    Rb = (float*)(smu + RB_OFF);
    const int tid = threadIdx.x;
    const int bh = blockIdx.y;
    const int b = bh >> 4, hh = bh & 15;
    const int m0 = blockIdx.x * 128;
    const int wid = tid >> 5, lane = tid & 31;
    const int g = lane >> 2, t = lane & 3;
    const int r0 = wid * 16 + g;
    const int r1 = r0 + 8;
    const int gm0 = m0 + r0, gm1 = m0 + r1;
    const unsigned* Khw = (const unsigned*)g_K + (size_t)bh * NTOK2 * 32; // 32 w/tok
    const unsigned* Vhw = (const unsigned*)g_V + (size_t)bh * HD * (NTOK2 / 2);
    const float* Rbh = rcs + (size_t)bh * NTOK * NTOK;
    const float* ad0p = addn + (size_t)(gm0 < NTOK ? gm0 : 0) * NTOK;
    const float* ad1p = addn + (size_t)(gm1 < NTOK ? gm1 : 0) * NTOK;
    const uint32_t su = (uint32_t)__cvta_generic_to_shared(smu);

    // Km fill: 128 tokens x 32 words; 2 threads/row, 16 words each.
    {
        int row = tid >> 1, ch = (tid & 1) * 16;
        unsigned* dst = Km + row * LDKM + ch;
        if (m0 + row < NTOK) {
            const unsigned* src = Khw + (size_t)(m0 + row) * 32 + ch;
#pragma unroll
            for (int q = 0; q < 4; q++)
                *(uint4*)(dst + q * 4) = *(const uint4*)(src + q * 4);
        } else {
#pragma unroll
            for (int q = 0; q < 4; q++)
                *(uint4*)(dst + q * 4) = make_uint4(0u, 0u, 0u, 0u);
        }
    }

    float accS[8][4];
    float accP[8][4], accR[8][4];
#pragma unroll
    for (int nt = 0; nt < 8; nt++)
#pragma unroll
        for (int q = 0; q < 4; q++) { accP[nt][q] = 0.f; accR[nt][q] = 0.f; }
    float rs0 = 0.f, rs1 = 0.f;

    for (int it = 0; it < 17; it++) {
        const int n0 = it * 64;
        __syncthreads();   // prev iter reads done; Km visible on it=0

        // group 0: Kn (64 tok x 32 w) + Vs (64 d x 32 w); 8 words/thread each
        {
            int row = tid >> 2, ch = (tid & 3) * 8;
            const unsigned* src = Khw + (size_t)(n0 + row) * 32 + ch;
            uint32_t dst = su + (KN_OFF + row * LDKN + ch) * 4;
            cpasync16(dst, src, 16);
            cpasync16(dst + 16, src + 4, 16);
        }
        {
            int d = tid >> 2, ch = (tid & 3) * 8;
            const unsigned* src = Vhw + (size_t)d * (NTOK2 / 2) + (n0 >> 1) + ch;
            uint32_t dst = su + (VS_OFF + d * LDVS + ch) * 4;
            cpasync16(dst, src, 16);
            cpasync16(dst + 16, src + 4, 16);
        }
        asm volatile("cp.async.commit_group;");

        // group 1: rcs tile 128 x 64 fp32
#pragma unroll
        for (int i = 0; i < 8; i++) {
            int c = tid + i * 256;
            int row = c >> 4, ch = (c & 15) * 4;
            int mm = m0 + row, nn = n0 + ch;
            int ok = (mm < NTOK) && (nn < NTOK);
            cpasync16(su + (RB_OFF + row * LDR + ch) * 4,
                      Rbh + (size_t)(ok ? mm : 0) * NTOK + (ok ? nn : 0), ok ? 16 : 0);
        }
        asm volatile("cp.async.commit_group;");

        asm volatile("cp.async.wait_group 1;");
        __syncthreads();

        // ---- GEMM1: accS(16x64) = Km . Kn^T (4 k16 groups over d=64) ----
#pragma unroll
        for (int nt = 0; nt < 8; nt++)
#pragma unroll
            for (int q = 0; q < 4; q++) accS[nt][q] = 0.f;
#pragma unroll
        for (int kg = 0; kg < 4; kg++) {
            unsigned a0 = Km[r0 * LDKM + kg * 8 + t];
            unsigned a1 = Km[r1 * LDKM + kg * 8 + t];
            unsigned a2 = Km[r0 * LDKM + kg * 8 + t + 4];
            unsigned a3 = Km[r1 * LDKM + kg * 8 + t + 4];
#pragma unroll
            for (int nt = 0; nt < 8; nt++) {
                unsigned b0 = Kn[(nt * 8 + g) * LDKN + kg * 8 + t];
                unsigned b1 = Kn[(nt * 8 + g) * LDKN + kg * 8 + t + 4];
                mma_f16(accS[nt], a0, a1, a2, a3, b0, b1);
            }
        }

        // ---- exp epilogue + rowsum partials ----
#pragma unroll
        for (int nt = 0; nt < 8; nt++) {
            int n = n0 + nt * 8 + 2 * t;
            if (n < NTOK) {
                float e0 = 0.f, e1 = 0.f, e2 = 0.f, e3 = 0.f;
                if (gm0 < NTOK) {
                    float2 a = *(const float2*)(ad0p + n);
                    e0 = __expf(SCALE * accS[nt][0] + a.x);
                    e1 = __expf(SCALE * accS[nt][1] + a.y);
                }
                if (gm1 < NTOK) {
                    float2 a = *(const float2*)(ad1p + n);
                    e2 = __expf(SCALE * accS[nt][2] + a.x);
                    e3 = __expf(SCALE * accS[nt][3] + a.y);
                }
                accS[nt][0] = e0; accS[nt][1] = e1;
                accS[nt][2] = e2; accS[nt][3] = e3;
                rs0 += e0 + e1; rs1 += e2 + e3;
            } else {
                accS[nt][0] = 0.f; accS[nt][1] = 0.f;
                accS[nt][2] = 0.f; accS[nt][3] = 0.f;
            }
        }

        asm volatile("cp.async.wait_group 0;");
        __syncthreads();

        // ---- fused GEMM2 (P@V) + GEMM3 (rcs@V): 4 k16 groups over tokens ----
#pragma unroll
        for (int j = 0; j < 4; j++) {
            unsigned pa0 = f16x2(accS[2 * j][0],     accS[2 * j][1]);
            unsigned pa1 = f16x2(accS[2 * j][2],     accS[2 * j][3]);
            unsigned pa2 = f16x2(accS[2 * j + 1][0], accS[2 * j + 1][1]);
            unsigned pa3 = f16x2(accS[2 * j + 1][2], accS[2 * j + 1][3]);
            float2 q0 = *(const float2*)(Rb + r0 * LDR + j * 16 + 2 * t);
            float2 q1 = *(const float2*)(Rb + r1 * LDR + j * 16 + 2 * t);
            float2 q2 = *(const float2*)(Rb + r0 * LDR + j * 16 + 8 + 2 * t);
            float2 q3 = *(const float2*)(Rb + r1 * LDR + j * 16 + 8 + 2 * t);
            unsigned ra0 = f16x2(q0.x, q0.y);
            unsigned ra1 = f16x2(q1.x, q1.y);
            unsigned ra2 = f16x2(q2.x, q2.y);
            unsigned ra3 = f16x2(q3.x, q3.y);
#pragma unroll
            for (int nt = 0; nt < 8; nt++) {
                unsigned b0 = Vs[(nt * 8 + g) * LDVS + j * 8 + t];
                unsigned b1 = Vs[(nt * 8 + g) * LDVS + j * 8 + t + 4];
                mma_f16(accP[nt], pa0, pa1, pa2, pa3, b0, b1);
                mma_f16(accR[nt], ra0, ra1, ra2, ra3, b0, b1);
            }
        }
    }

    // ---- final epilogue: normalize + mix + store fp32 to g_O ----
    rs0 += __shfl_xor_sync(0xffffffffu, rs0, 1);
    rs0 += __shfl_xor_sync(0xffffffffu, rs0, 2);
    rs1 += __shfl_xor_sync(0xffffffffu, rs1, 1);
    rs1 += __shfl_xor_sync(0xffffffffu, rs1, 2);
    const float inv0 = W_SOFT / rs0, inv1 = W_SOFT / rs1;

    if (gm0 < NTOK) {
        float* op = g_O + ((size_t)b * NTOK + gm0) * C_ + hh * HD;
#pragma unroll
        for (int nt = 0; nt < 8; nt++) {
            int d = nt * 8 + 2 * t;
            float2 v = make_float2(accP[nt][0] * inv0 + W_RCS * accR[nt][0],
                                   accP[nt][1] * inv0 + W_RCS * accR[nt][1]);
            *(float2*)(op + d) = v;
        }
    }
    if (gm1 < NTOK) {
        float* op = g_O + ((size_t)b * NTOK + gm1) * C_ + hh * HD;
#pragma unroll
        for (int nt = 0; nt < 8; nt++) {
            int d = nt * 8 + 2 * t;
            float2 v = make_float2(accP[nt][2] * inv1 + W_RCS * accR[nt][2],
                                   accP[nt][3] * inv1 + W_RCS * accR[nt][3]);
            *(float2*)(op + d) = v;
        }
    }
}

// ---------------------------------------------------------------------------
extern "C" void kernel_launch(void* const* d_in, const int* in_sizes, int n_in,
                              void* d_out, int out_size)
{
    const float* x      = (const float*)d_in[0];
    const float* qkv_w  = (const float*)d_in[1];
    const float* qkv_b  = (const float*)d_in[2];
    const float* proj_w = (const float*)d_in[3];
    const float* proj_b = (const float*)d_in[4];
    const float* addn   = (const float*)d_in[5];
    const float* rcs    = (const float*)d_in[6];
    float* out = (float*)d_out;

    cudaFuncSetAttribute(kv_proj_kernel,
                         cudaFuncAttributeMaxDynamicSharedMemorySize,
                         GEMM_SMEM_WORDS * 4);
    cudaFuncSetAttribute(proj_kernel,
                         cudaFuncAttributeMaxDynamicSharedMemorySize,
                         GEMM_SMEM_WORDS * 4);
    cudaFuncSetAttribute(attn_fused_kernel,
                         cudaFuncAttributeMaxDynamicSharedMemorySize,
                         ATT_WORDS * 4);

    kv_proj_kernel<<<dim3(16, 33), 256, GEMM_SMEM_WORDS * 4>>>(x, qkv_w, qkv_b);
    attn_fused_kernel<<<dim3(9, 64), 256, ATT_WORDS * 4>>>(addn, rcs);
    proj_kernel<<<dim3(8, 33), 256, GEMM_SMEM_WORDS * 4>>>(proj_w, proj_b, out);
}

// round 15
// speedup vs baseline: 1.1477x; 1.0078x over previous
#include <cuda_runtime.h>
#include <cuda_fp16.h>
#include <cstdint>
#include <math.h>

// Problem constants
#define B_    4
#define NTOK  1032
#define NTOK2 1088
#define C_    1024
#define H_    16
#define HD    64
#define BH    64
#define M_ALL 4128
#define SCALE 0.125f
#define W_SOFT 0.8f
#define W_RCS  1.2f

// GEMM smem: 2 buffers, stage = 128 rows x 32 floats, row stride 36 words
#define GLD   36
#define GSTG  (128 * GLD)                 // 4608 words per operand-stage
#define G_BAR (4 * GSTG)                  // word offset of barriers
#define GEMM_SMEM_BYTES ((4 * GSTG + 8) * 4)   // 73760 B
#define G_SBYTES 32768u                   // bytes per stage (A 16K + B 16K)

// attn smem (words)
#define LDKM 36
#define LDKN 36
#define LDVS 36
#define LDR  68
#define KM_OFF 0
#define KN_OFF (128 * LDKM)
#define VS_OFF (KN_OFF + 64 * LDKN)
#define RB_OFF (VS_OFF + 64 * LDVS)
#define AT_BAR (RB_OFF + 128 * LDR)       // 17920
#define ATT_SMEM_BYTES ((AT_BAR + 8) * 4) // 71712 B

// Scratch (zero-initialized)
__device__ __half g_K[(size_t)BH * NTOK2 * HD];   // [bh][tok(1088)][d]
__device__ __half g_V[(size_t)BH * HD * NTOK2];   // [bh][d][tok(1088)]
__device__ float  g_O[(size_t)M_ALL * C_];

// ---------------------------------------------------------------------------
__device__ __forceinline__ unsigned f16x2(float lo, float hi) {
    unsigned r;
    asm("cvt.rn.f16x2.f32 %0, %1, %2;" : "=r"(r) : "f"(hi), "f"(lo));
    return r;
}
__device__ __forceinline__ void mma_f16(float* c, unsigned a0, unsigned a1,
                                        unsigned a2, unsigned a3,
                                        unsigned b0, unsigned b1) {
    asm volatile(
        "mma.sync.aligned.m16n8k16.row.col.f32.f16.f16.f32 "
        "{%0,%1,%2,%3},{%4,%5,%6,%7},{%8,%9},{%0,%1,%2,%3};"
        : "+f"(c[0]), "+f"(c[1]), "+f"(c[2]), "+f"(c[3])
        : "r"(a0), "r"(a1), "r"(a2), "r"(a3), "r"(b0), "r"(b1));
}
__device__ __forceinline__ void cpasync16(uint32_t dst, const void* src, int sbytes) {
    asm volatile("cp.async.cg.shared.global [%0], [%1], 16, %2;"
                 :: "r"(dst), "l"(src), "r"(sbytes));
}
__device__ __forceinline__ void bulkcp(uint32_t dst, const void* src,
                                       unsigned bytes, uint32_t bar) {
    asm volatile(
        "cp.async.bulk.shared::cluster.global.mbarrier::complete_tx::bytes "
        "[%0], [%1], %2, [%3];"
        :: "r"(dst), "l"(src), "r"(bytes), "r"(bar) : "memory");
}
#define MBAR_INIT(a, c) \
    asm volatile("mbarrier.init.shared.b64 [%0], %1;" :: "r"(a), "r"(c) : "memory")
#define MBAR_EXPECT(a, b) \
    asm volatile("mbarrier.arrive.expect_tx.shared.b64 _, [%0], %1;" \
                 :: "r"(a), "r"(b) : "memory")
#define MBAR_WAIT(a, ph) do { \
    uint32_t _m = (a), _p = (ph), _d; \
    asm volatile( \
        "{\n\t.reg .pred p;\n\t" \
        "mbarrier.try_wait.parity.acquire.cta.shared::cta.b64 p, [%1], %2;\n\t" \
        "selp.b32 %0, 1, 0, p;\n\t}" : "=r"(_d) : "r"(_m), "r"(_p) : "memory"); \
    if (!_d) { \
        asm volatile( \
            "{\n\t.reg .pred P1;\n\t" \
            "WL_%=:\n\t" \
            "mbarrier.try_wait.parity.acquire.cta.shared::cta.b64 P1, [%0], %1, 0x989680;\n\t" \
            "@P1 bra.uni WD_%=;\n\t" \
            "bra.uni WL_%=;\n\t" \
            "WD_%=:\n\t}" :: "r"(_m), "r"(_p) : "memory"); \
    } \
} while (0)

// ---------------------------------------------------------------------------
// GEMM mainloop: 128x128 tile, fp32 operands in global, fp16 mma.
// K=1024 in 32 stages of BK=32. Bulk-copy fill (one 128B row per thread).
// ---------------------------------------------------------------------------
__device__ __forceinline__ void wg_gemm_bulk(
    const float* __restrict__ Abase,   // row-clamped base (stride C_)
    const float* __restrict__ Bbase,
    int arow_idx, int brow_idx,        // this thread's row (A if tid<128)
    float* smem, float acc[4][4][4], int wm, int wn, int g, int t)
{
    const int tid = threadIdx.x;
    const uint32_t su = (uint32_t)__cvta_generic_to_shared(smem);
    const uint32_t bar0 = su + G_BAR * 4;
    const uint32_t bar1 = bar0 + 8;

    if (tid == 0) { MBAR_INIT(bar0, 1); MBAR_INIT(bar1, 1); }
    __syncthreads();
    if (tid == 0) { MBAR_EXPECT(bar0, G_SBYTES); MBAR_EXPECT(bar1, G_SBYTES); }
    __syncthreads();

    const bool isA = (tid < 128);
    const float* srcRow = isA ? (Abase + (size_t)arow_idx * C_)
                              : (Bbase + (size_t)brow_idx * C_);
    const int rowLocal = isA ? tid : (tid - 128);
    // buf s: A at (s&1)*GSTG, B at 2*GSTG + (s&1)*GSTG
    const uint32_t dstBase = su + ((isA ? 0 : 2 * GSTG) + rowLocal * GLD) * 4;

    // prologue: stages 0 and 1
    bulkcp(dstBase,            srcRow,       128u, bar0);
    bulkcp(dstBase + GSTG * 4, srcRow + 32,  128u, bar1);

    for (int kt = 0; kt < 32; kt++) {
        const int buf = kt & 1;
        MBAR_WAIT(buf ? bar1 : bar0, (kt >> 1) & 1);

        const float* Af = smem + buf * GSTG;
        const float* Bf = smem + 2 * GSTG + buf * GSTG;
#pragma unroll
        for (int kg = 0; kg < 2; kg++) {
            unsigned a[4][4], bb[4][2];
#pragma unroll
            for (int mt = 0; mt < 4; mt++) {
                const float* ap = Af + (wm + mt * 16 + g) * GLD + kg * 16 + 2 * t;
                float2 p0 = *(const float2*)ap;
                float2 p1 = *(const float2*)(ap + 8 * GLD);
                float2 p2 = *(const float2*)(ap + 8);
                float2 p3 = *(const float2*)(ap + 8 * GLD + 8);
                a[mt][0] = f16x2(p0.x, p0.y);
                a[mt][1] = f16x2(p1.x, p1.y);
                a[mt][2] = f16x2(p2.x, p2.y);
                a[mt][3] = f16x2(p3.x, p3.y);
            }
#pragma unroll
            for (int nt = 0; nt < 4; nt++) {
                const float* bp = Bf + (wn + nt * 8 + g) * GLD + kg * 16 + 2 * t;
                float2 q0 = *(const float2*)bp;
                float2 q1 = *(const float2*)(bp + 8);
                bb[nt][0] = f16x2(q0.x, q0.y);
                bb[nt][1] = f16x2(q1.x, q1.y);
            }
#pragma unroll
            for (int mt = 0; mt < 4; mt++)
#pragma unroll
                for (int nt = 0; nt < 4; nt++)
                    mma_f16(acc[mt][nt], a[mt][0], a[mt][1], a[mt][2], a[mt][3],
                            bb[nt][0], bb[nt][1]);
        }

        if (kt + 2 < 32) {
            __syncthreads();   // all threads done reading buf
            if (tid == 0) MBAR_EXPECT(buf ? bar1 : bar0, G_SBYTES);
            __syncthreads();
            bulkcp(dstBase + buf * GSTG * 4, srcRow + (kt + 2) * 32, 128u,
                   buf ? bar1 : bar0);
        }
    }
}

// ---------------------------------------------------------------------------
// Kernel 1: K,V projection. Grid (16, 33), 256 threads.
// ---------------------------------------------------------------------------
__global__ __launch_bounds__(256) void kv_proj_kernel(
    const float* __restrict__ x, const float* __restrict__ qkv_w,
    const float* __restrict__ qkv_b)
{
    extern __shared__ float sm_kv[];
    const int tid = threadIdx.x;
    const int m0 = blockIdx.y * 128, j0 = blockIdx.x * 128;
    const int wid = tid >> 5, lane = tid & 31;
    const int g = lane >> 2, t = lane & 3;
    const int wm = (wid >> 2) * 64, wn = (wid & 3) * 32;
    const float* Wk = qkv_w + (size_t)C_ * C_;

    int arow = m0 + tid; if (arow >= M_ALL) arow = M_ALL - 1;   // clamp (tid<128 used)
    int brow = j0 + (tid - 128);
    if (brow < 0) brow = 0;

    float acc[4][4][4];
#pragma unroll
    for (int a = 0; a < 4; a++)
#pragma unroll
        for (int b = 0; b < 4; b++)
#pragma unroll
            for (int c = 0; c < 4; c++) acc[a][b][c] = 0.f;

    wg_gemm_bulk(x, Wk, arow, brow, sm_kv, acc, wm, wn, g, t);

#pragma unroll
    for (int mt = 0; mt < 4; mt++) {
#pragma unroll
        for (int h = 0; h < 2; h++) {
            int m = m0 + wm + mt * 16 + g + h * 8;
            if (m >= M_ALL) continue;
            int b = m / NTOK, n = m - b * NTOK;
#pragma unroll
            for (int nt = 0; nt < 4; nt++) {
                int j = j0 + wn + nt * 8 + t * 2;
#pragma unroll
                for (int c = 0; c < 2; c++) {
                    int jj = j + c;
                    float v = acc[mt][nt][h * 2 + c] + qkv_b[C_ + jj];
                    if (jj < C_) {
                        int hh = jj >> 6, d = jj & 63;
                        g_K[(((size_t)b * H_ + hh) * NTOK2 + n) * HD + d] =
                            __float2half_rn(v);
                    } else {
                        int j2 = jj - C_;
                        int hh = j2 >> 6, d = j2 & 63;
                        g_V[(((size_t)b * H_ + hh) * HD + d) * NTOK2 + n] =
                            __float2half_rn(v);
                    }
                }
            }
        }
    }
}

// ---------------------------------------------------------------------------
// Kernel 3: output projection. Grid (8, 33), 256 threads.
// ---------------------------------------------------------------------------
__global__ __launch_bounds__(256) void proj_kernel(
    const float* __restrict__ proj_w, const float* __restrict__ proj_b,
    float* __restrict__ out)
{
    extern __shared__ float sm_pj[];
    const int tid = threadIdx.x;
    const int m0 = blockIdx.y * 128, j0 = blockIdx.x * 128;
    const int wid = tid >> 5, lane = tid & 31;
    const int g = lane >> 2, t = lane & 3;
    const int wm = (wid >> 2) * 64, wn = (wid & 3) * 32;

    int arow = m0 + tid; if (arow >= M_ALL) arow = M_ALL - 1;
    int brow = j0 + (tid - 128);
    if (brow < 0) brow = 0;

    float acc[4][4][4];
#pragma unroll
    for (int a = 0; a < 4; a++)
#pragma unroll
        for (int b = 0; b < 4; b++)
#pragma unroll
            for (int c = 0; c < 4; c++) acc[a][b][c] = 0.f;

    wg_gemm_bulk(g_O, proj_w, arow, brow, sm_pj, acc, wm, wn, g, t);

#pragma unroll
    for (int mt = 0; mt < 4; mt++) {
#pragma unroll
        for (int h = 0; h < 2; h++) {
            int m = m0 + wm + mt * 16 + g + h * 8;
            if (m >= M_ALL) continue;
#pragma unroll
            for (int nt = 0; nt < 4; nt++) {
                int j = j0 + wn + nt * 8 + t * 2;
                float2 v = make_float2(acc[mt][nt][h * 2 + 0] + proj_b[j],
                                       acc[mt][nt][h * 2 + 1] + proj_b[j + 1]);
                *(float2*)(out + (size_t)m * C_ + j) = v;
            }
        }
    }
}

// ---------------------------------------------------------------------------
// Kernel 2: fused attention (R14 math; bulk-copy tile fills).
// ---------------------------------------------------------------------------
__global__ __launch_bounds__(256, 2) void attn_fused_kernel(
    const float* __restrict__ addn, const float* __restrict__ rcs)
{
    extern __shared__ unsigned smu[];
    unsigned* Km = smu + KM_OFF;
    unsigned* Kn = smu + KN_OFF;
    unsigned* Vs = smu + VS_OFF;
    float*    Rb = (float*)(smu + RB_OFF);
    const int tid = threadIdx.x;
    const int bh = blockIdx.y;
    const int b = bh >> 4, hh = bh & 15;
    const int m0 = blockIdx.x * 128;
    const int wid = tid >> 5, lane = tid & 31;
    const int g = lane >> 2, t = lane & 3;
    const int r0 = wid * 16 + g;
    const int r1 = r0 + 8;
    const int gm0 = m0 + r0, gm1 = m0 + r1;
    const unsigned* Khw = (const unsigned*)g_K + (size_t)bh * NTOK2 * 32;
    const __half*   Vhh = g_V + (size_t)bh * HD * NTOK2;
    const float* Rbh = rcs + (size_t)bh * NTOK * NTOK;
    const float* ad0p = addn + (size_t)(gm0 < NTOK ? gm0 : 0) * NTOK;
    const float* ad1p = addn + (size_t)(gm1 < NTOK ? gm1 : 0) * NTOK;
    const uint32_t su = (uint32_t)__cvta_generic_to_shared(smu);
    const uint32_t kvbar = su + AT_BAR * 4;
    const uint32_t rcbar = kvbar + 8;

    if (tid == 0) { MBAR_INIT(kvbar, 1); MBAR_INIT(rcbar, 1); }

    // Km fill: 128 tokens x 32 words; 2 threads/row, 16 words each.
    {
        int row = tid >> 1, ch = (tid & 1) * 16;
        unsigned* dst = Km + row * LDKM + ch;
        if (m0 + row < NTOK) {
            const unsigned* src = Khw + (size_t)(m0 + row) * 32 + ch;
#pragma unroll
            for (int q = 0; q < 4; q++)
                *(uint4*)(dst + q * 4) = *(const uint4*)(src + q * 4);
        } else {
#pragma unroll
            for (int q = 0; q < 4; q++)
                *(uint4*)(dst + q * 4) = make_uint4(0u, 0u, 0u, 0u);
        }
    }

    float accS[8][4];
    float accP[8][4], accR[8][4];
#pragma unroll
    for (int nt = 0; nt < 8; nt++)
#pragma unroll
        for (int q = 0; q < 4; q++) { accP[nt][q] = 0.f; accR[nt][q] = 0.f; }
    float rs0 = 0.f, rs1 = 0.f;

    for (int it = 0; it < 17; it++) {
        const int n0 = it * 64;
        const bool last = (it == 16);
        __syncthreads();   // prev compute done; Km + mbarriers ready on it=0

        if (tid == 0) {
            MBAR_EXPECT(kvbar, 16384u);
            if (!last) MBAR_EXPECT(rcbar, 32768u);
        }
        __syncthreads();

        if (tid < 64) {
            // Kn row: token n0+tid, 128 B
            bulkcp(su + (KN_OFF + tid * LDKN) * 4,
                   Khw + (size_t)(n0 + tid) * 32, 128u, kvbar);
        } else if (tid < 128) {
            int d = tid - 64;
            bulkcp(su + (VS_OFF + d * LDVS) * 4,
                   Vhh + (size_t)d * NTOK2 + n0, 128u, kvbar);
        } else if (!last) {
            int row = tid - 128;
            int mm = m0 + row; if (mm >= NTOK) mm = NTOK - 1;   // clamp (discarded)
            bulkcp(su + (RB_OFF + row * LDR) * 4,
                   Rbh + (size_t)mm * NTOK + n0, 256u, rcbar);
        }
        if (last) {
            // masked cp16 fill of Rb for the partial tile (cols >= NTOK -> 0)
#pragma unroll
            for (int i = 0; i < 8; i++) {
                int c = tid + i * 256;
                int row = c >> 4, ch = (c & 15) * 4;
                int mm = m0 + row, nn = n0 + ch;
                int ok = (mm < NTOK) && (nn < NTOK);
                cpasync16(su + (RB_OFF + row * LDR + ch) * 4,
                          Rbh + (size_t)(ok ? mm : 0) * NTOK + (ok ? nn : 0),
                          ok ? 16 : 0);
            }
            asm volatile("cp.async.commit_group;");
        }

        MBAR_WAIT(kvbar, it & 1);

        // ---- GEMM1: accS(16x64) = Km . Kn^T ----
#pragma unroll
        for (int nt = 0; nt < 8; nt++)
#pragma unroll
            for (int q = 0; q < 4; q++) accS[nt][q] = 0.f;
#pragma unroll
        for (int kg = 0; kg < 4; kg++) {
            unsigned a0 = Km[r0 * LDKM + kg * 8 + t];
            unsigned a1 = Km[r1 * LDKM + kg * 8 + t];
            unsigned a2 = Km[r0 * LDKM + kg * 8 + t + 4];
            unsigned a3 = Km[r1 * LDKM + kg * 8 + t + 4];
#pragma unroll
            for (int nt = 0; nt < 8; nt++) {
                unsigned b0 = Kn[(nt * 8 + g) * LDKN + kg * 8 + t];
                unsigned b1 = Kn[(nt * 8 + g) * LDKN + kg * 8 + t + 4];
                mma_f16(accS[nt], a0, a1, a2, a3, b0, b1);
            }
        }

        // ---- exp epilogue + rowsum partials ----
#pragma unroll
        for (int nt = 0; nt < 8; nt++) {
            int n = n0 + nt * 8 + 2 * t;
            if (n < NTOK) {
                float e0 = 0.f, e1 = 0.f, e2 = 0.f, e3 = 0.f;
                if (gm0 < NTOK) {
                    float2 a = *(const float2*)(ad0p + n);
                    e0 = __expf(SCALE * accS[nt][0] + a.x);
                    e1 = __expf(SCALE * accS[nt][1] + a.y);
                }
                if (gm1 < NTOK) {
                    float2 a = *(const float2*)(ad1p + n);
                    e2 = __expf(SCALE * accS[nt][2] + a.x);
                    e3 = __expf(SCALE * accS[nt][3] + a.y);
                }
                accS[nt][0] = e0; accS[nt][1] = e1;
                accS[nt][2] = e2; accS[nt][3] = e3;
                rs0 += e0 + e1; rs1 += e2 + e3;
            } else {
                accS[nt][0] = 0.f; accS[nt][1] = 0.f;
                accS[nt][2] = 0.f; accS[nt][3] = 0.f;
            }
        }

        if (!last) {
            MBAR_WAIT(rcbar, it & 1);
        } else {
            asm volatile("cp.async.wait_group 0;");
            __syncthreads();
        }

        // ---- fused GEMM2 (P@V) + GEMM3 (rcs@V) ----
#pragma unroll
        for (int j = 0; j < 4; j++) {
            unsigned pa0 = f16x2(accS[2 * j][0],     accS[2 * j][1]);
            unsigned pa1 = f16x2(accS[2 * j][2],     accS[2 * j][3]);
            unsigned pa2 = f16x2(accS[2 * j + 1][0], accS[2 * j + 1][1]);
            unsigned pa3 = f16x2(accS[2 * j + 1][2], accS[2 * j + 1][3]);
            float2 q0 = *(const float2*)(Rb + r0 * LDR + j * 16 + 2 * t);
            float2 q1 = *(const float2*)(Rb + r1 * LDR + j * 16 + 2 * t);
            float2 q2 = *(const float2*)(Rb + r0 * LDR + j * 16 + 8 + 2 * t);
            float2 q3 = *(const float2*)(Rb + r1 * LDR + j * 16 + 8 + 2 * t);
            unsigned ra0 = f16x2(q0.x, q0.y);
            unsigned ra1 = f16x2(q1.x, q1.y);
            unsigned ra2 = f16x2(q2.x, q2.y);
            unsigned ra3 = f16x2(q3.x, q3.y);
#pragma unroll
            for (int nt = 0; nt < 8; nt++) {
                unsigned b0 = Vs[(nt * 8 + g) * LDVS + j * 8 + t];
                unsigned b1 = Vs[(nt * 8 + g) * LDVS + j * 8 + t + 4];
                mma_f16(accP[nt], pa0, pa1, pa2, pa3, b0, b1);
                mma_f16(accR[nt], ra0, ra1, ra2, ra3, b0, b1);
            }
        }
    }

    // ---- final epilogue ----
    rs0 += __shfl_xor_sync(0xffffffffu, rs0, 1);
    rs0 += __shfl_xor_sync(0xffffffffu, rs0, 2);
    rs1 += __shfl_xor_sync(0xffffffffu, rs1, 1);
    rs1 += __shfl_xor_sync(0xffffffffu, rs1, 2);
    const float inv0 = W_SOFT / rs0, inv1 = W_SOFT / rs1;

    if (gm0 < NTOK) {
        float* op = g_O + ((size_t)b * NTOK + gm0) * C_ + hh * HD;
#pragma unroll
        for (int nt = 0; nt < 8; nt++) {
            int d = nt * 8 + 2 * t;
            float2 v = make_float2(accP[nt][0] * inv0 + W_RCS * accR[nt][0],
                                   accP[nt][1] * inv0 + W_RCS * accR[nt][1]);
            *(float2*)(op + d) = v;
        }
    }
    if (gm1 < NTOK) {
        float* op = g_O + ((size_t)b * NTOK + gm1) * C_ + hh * HD;
#pragma unroll
        for (int nt = 0; nt < 8; nt++) {
            int d = nt * 8 + 2 * t;
            float2 v = make_float2(accP[nt][2] * inv1 + W_RCS * accR[nt][2],
                                   accP[nt][3] * inv1 + W_RCS * accR[nt][3]);
            *(float2*)(op + d) = v;
        }
    }
}

// ---------------------------------------------------------------------------
extern "C" void kernel_launch(void* const* d_in, const int* in_sizes, int n_in,
                              void* d_out, int out_size)
{
    const float* x      = (const float*)d_in[0];
    const float* qkv_w  = (const float*)d_in[1];
    const float* qkv_b  = (const float*)d_in[2];
    const float* proj_w = (const float*)d_in[3];
    const float* proj_b = (const float*)d_in[4];
    const float* addn   = (const float*)d_in[5];
    const float* rcs    = (const float*)d_in[6];
    float* out = (float*)d_out;

    cudaFuncSetAttribute(kv_proj_kernel,
                         cudaFuncAttributeMaxDynamicSharedMemorySize,
                         GEMM_SMEM_BYTES);
    cudaFuncSetAttribute(proj_kernel,
                         cudaFuncAttributeMaxDynamicSharedMemorySize,
                         GEMM_SMEM_BYTES);
    cudaFuncSetAttribute(attn_fused_kernel,
                         cudaFuncAttributeMaxDynamicSharedMemorySize,
                         ATT_SMEM_BYTES);

    kv_proj_kernel<<<dim3(16, 33), 256, GEMM_SMEM_BYTES>>>(x, qkv_w, qkv_b);
    attn_fused_kernel<<<dim3(9, 64), 256, ATT_SMEM_BYTES>>>(addn, rcs);
    proj_kernel<<<dim3(8, 33), 256, GEMM_SMEM_BYTES>>>(proj_w, proj_b, out);
}

// round 16
// speedup vs baseline: 1.3289x; 1.1580x over previous
#include <cuda_runtime.h>
#include <cuda_fp16.h>
#include <cstdint>
#include <math.h>

// Problem constants
#define B_    4
#define NTOK  1032
#define NTOK2 1088
#define C_    1024
#define H_    16
#define HD    64
#define BH    64
#define M_ALL 4128
#define SCALE 0.125f
#define W_SOFT 0.8f
#define W_RCS  1.2f

// GEMM smem (words):
//  F32 staging: A [128][36] at 0, B [128][36] at 4608   (single buffer)
//  H16 tiles:   2 bufs x (A [128][20] + B [128][20]) at 9216, buf stride 5120
//  mbarrier at word 19456
#define F32LD 36
#define F32B_OFF 4608
#define H_OFF 9216
#define HLD 20
#define HBUF 5120
#define GBAR_OFF 19456
#define GEMM_SMEM_BYTES ((GBAR_OFF + 4) * 4)   // 77840 B
#define G_SBYTES 32768u

// attn smem (words) — R15 verbatim
#define LDKM 36
#define LDKN 36
#define LDVS 36
#define LDR  68
#define KM_OFF 0
#define KN_OFF (128 * LDKM)
#define VS_OFF (KN_OFF + 64 * LDKN)
#define RB_OFF (VS_OFF + 64 * LDVS)
#define AT_BAR (RB_OFF + 128 * LDR)
#define ATT_SMEM_BYTES ((AT_BAR + 8) * 4)

// Scratch (zero-initialized)
__device__ __half g_K[(size_t)BH * NTOK2 * HD];   // [bh][tok(1088)][d]
__device__ __half g_V[(size_t)BH * HD * NTOK2];   // [bh][d][tok(1088)]
__device__ float  g_O[(size_t)M_ALL * C_];

// ---------------------------------------------------------------------------
__device__ __forceinline__ unsigned f16x2(float lo, float hi) {
    unsigned r;
    asm("cvt.rn.f16x2.f32 %0, %1, %2;" : "=r"(r) : "f"(hi), "f"(lo));
    return r;
}
__device__ __forceinline__ void mma_f16(float* c, unsigned a0, unsigned a1,
                                        unsigned a2, unsigned a3,
                                        unsigned b0, unsigned b1) {
    asm volatile(
        "mma.sync.aligned.m16n8k16.row.col.f32.f16.f16.f32 "
        "{%0,%1,%2,%3},{%4,%5,%6,%7},{%8,%9},{%0,%1,%2,%3};"
        : "+f"(c[0]), "+f"(c[1]), "+f"(c[2]), "+f"(c[3])
        : "r"(a0), "r"(a1), "r"(a2), "r"(a3), "r"(b0), "r"(b1));
}
__device__ __forceinline__ void cpasync16(uint32_t dst, const void* src, int sbytes) {
    asm volatile("cp.async.cg.shared.global [%0], [%1], 16, %2;"
                 :: "r"(dst), "l"(src), "r"(sbytes));
}
__device__ __forceinline__ void bulkcp(uint32_t dst, const void* src,
                                       unsigned bytes, uint32_t bar) {
    asm volatile(
        "cp.async.bulk.shared::cluster.global.mbarrier::complete_tx::bytes "
        "[%0], [%1], %2, [%3];"
        :: "r"(dst), "l"(src), "r"(bytes), "r"(bar) : "memory");
}
#define MBAR_INIT(a, c) \
    asm volatile("mbarrier.init.shared.b64 [%0], %1;" :: "r"(a), "r"(c) : "memory")
#define MBAR_EXPECT(a, b) \
    asm volatile("mbarrier.arrive.expect_tx.shared.b64 _, [%0], %1;" \
                 :: "r"(a), "r"(b) : "memory")
#define MBAR_WAIT(a, ph) do { \
    uint32_t _m = (a), _p = (ph), _d; \
    asm volatile( \
        "{\n\t.reg .pred p;\n\t" \
        "mbarrier.try_wait.parity.acquire.cta.shared::cta.b64 p, [%1], %2;\n\t" \
        "selp.b32 %0, 1, 0, p;\n\t}" : "=r"(_d) : "r"(_m), "r"(_p) : "memory"); \
    if (!_d) { \
        asm volatile( \
            "{\n\t.reg .pred P1;\n\t" \
            "WL_%=:\n\t" \
            "mbarrier.try_wait.parity.acquire.cta.shared::cta.b64 P1, [%0], %1, 0x989680;\n\t" \
            "@P1 bra.uni WD_%=;\n\t" \
            "bra.uni WL_%=;\n\t" \
            "WD_%=:\n\t}" :: "r"(_m), "r"(_p) : "memory"); \
    } \
} while (0)

// ---------------------------------------------------------------------------
// GEMM mainloop: 128x128 tile, fp32 global operands, per-stage fp16 conversion.
// K=1024 in 32 stages of BK=32.
// ---------------------------------------------------------------------------
__device__ __forceinline__ void wg_gemm_cvt(
    const float* __restrict__ Abase, const float* __restrict__ Bbase,
    int arow_idx, int brow_idx,
    float* smem, float acc[4][4][4], int wm, int wn, int g, int t)
{
    const int tid = threadIdx.x;
    unsigned* smw = (unsigned*)smem;
    const uint32_t su = (uint32_t)__cvta_generic_to_shared(smem);
    const uint32_t bar = su + GBAR_OFF * 4;

    if (tid == 0) MBAR_INIT(bar, 1);
    __syncthreads();
    if (tid == 0) MBAR_EXPECT(bar, G_SBYTES);
    __syncthreads();

    const bool isA = (tid < 128);
    const float* srcRow = isA ? (Abase + (size_t)arow_idx * C_)
                              : (Bbase + (size_t)brow_idx * C_);
    const int rowLocal = isA ? tid : (tid - 128);
    const uint32_t dstF32 = su + ((isA ? 0 : F32B_OFF) + rowLocal * F32LD) * 4;

    bulkcp(dstF32, srcRow, 128u, bar);

    // conversion coords: row cr, half h (16 floats each of A and B rows)
    const int cr = tid >> 1, hch = (tid & 1) * 16;
    const float* fA = smem + cr * F32LD + hch;
    const float* fB = smem + F32B_OFF + cr * F32LD + hch;
    const int hoff = cr * HLD + (tid & 1) * 8;

    for (int s = 0; s < 32; s++) {
        MBAR_WAIT(bar, s & 1);

        // ---- convert stage: fp32 -> fp16 into H16[s&1] ----
        unsigned* hA = smw + H_OFF + (s & 1) * HBUF + hoff;
        unsigned* hB = hA + 2560;
        {
            float4 v0 = *(const float4*)(fA);
            float4 v1 = *(const float4*)(fA + 4);
            float4 v2 = *(const float4*)(fA + 8);
            float4 v3 = *(const float4*)(fA + 12);
            uint4 o;
            o.x = f16x2(v0.x, v0.y); o.y = f16x2(v0.z, v0.w);
            o.z = f16x2(v1.x, v1.y); o.w = f16x2(v1.z, v1.w);
            *(uint4*)hA = o;
            o.x = f16x2(v2.x, v2.y); o.y = f16x2(v2.z, v2.w);
            o.z = f16x2(v3.x, v3.y); o.w = f16x2(v3.z, v3.w);
            *(uint4*)(hA + 4) = o;
            v0 = *(const float4*)(fB);
            v1 = *(const float4*)(fB + 4);
            v2 = *(const float4*)(fB + 8);
            v3 = *(const float4*)(fB + 12);
            o.x = f16x2(v0.x, v0.y); o.y = f16x2(v0.z, v0.w);
            o.z = f16x2(v1.x, v1.y); o.w = f16x2(v1.z, v1.w);
            *(uint4*)hB = o;
            o.x = f16x2(v2.x, v2.y); o.y = f16x2(v2.z, v2.w);
            o.z = f16x2(v3.x, v3.y); o.w = f16x2(v3.z, v3.w);
            *(uint4*)(hB + 4) = o;
        }
        __syncthreads();   // conversion done; fp32 reads complete

        if (s + 1 < 32) {
            if (tid == 0) MBAR_EXPECT(bar, G_SBYTES);
            __syncthreads();
            bulkcp(dstF32, srcRow + (s + 1) * 32, 128u, bar);
        }

        // ---- compute from H16[s&1]: 2 x k16 ----
        const unsigned* Ah = smw + H_OFF + (s & 1) * HBUF;
        const unsigned* Bh = Ah + 2560;
#pragma unroll
        for (int kg = 0; kg < 2; kg++) {
            unsigned a[4][4], bb[4][2];
#pragma unroll
            for (int mt = 0; mt < 4; mt++) {
                const unsigned* ap = Ah + (wm + mt * 16 + g) * HLD + kg * 8 + t;
                a[mt][0] = ap[0];
                a[mt][1] = ap[8 * HLD];
                a[mt][2] = ap[4];
                a[mt][3] = ap[8 * HLD + 4];
            }
#pragma unroll
            for (int nt = 0; nt < 4; nt++) {
                const unsigned* bp = Bh + (wn + nt * 8 + g) * HLD + kg * 8 + t;
                bb[nt][0] = bp[0];
                bb[nt][1] = bp[4];
            }
#pragma unroll
            for (int mt = 0; mt < 4; mt++)
#pragma unroll
                for (int nt = 0; nt < 4; nt++)
                    mma_f16(acc[mt][nt], a[mt][0], a[mt][1], a[mt][2], a[mt][3],
                            bb[nt][0], bb[nt][1]);
        }
    }
}

// ---------------------------------------------------------------------------
// Kernel 1: K,V projection. Grid (16, 33), 256 threads.
// ---------------------------------------------------------------------------
__global__ __launch_bounds__(256) void kv_proj_kernel(
    const float* __restrict__ x, const float* __restrict__ qkv_w,
    const float* __restrict__ qkv_b)
{
    extern __shared__ float sm_kv[];
    const int tid = threadIdx.x;
    const int m0 = blockIdx.y * 128, j0 = blockIdx.x * 128;
    const int wid = tid >> 5, lane = tid & 31;
    const int g = lane >> 2, t = lane & 3;
    const int wm = (wid >> 2) * 64, wn = (wid & 3) * 32;
    const float* Wk = qkv_w + (size_t)C_ * C_;

    int arow = m0 + tid; if (arow >= M_ALL) arow = M_ALL - 1;
    int brow = j0 + (tid - 128);
    if (brow < 0) brow = 0;

    float acc[4][4][4];
#pragma unroll
    for (int a = 0; a < 4; a++)
#pragma unroll
        for (int b = 0; b < 4; b++)
#pragma unroll
            for (int c = 0; c < 4; c++) acc[a][b][c] = 0.f;

    wg_gemm_cvt(x, Wk, arow, brow, sm_kv, acc, wm, wn, g, t);

#pragma unroll
    for (int mt = 0; mt < 4; mt++) {
#pragma unroll
        for (int h = 0; h < 2; h++) {
            int m = m0 + wm + mt * 16 + g + h * 8;
            if (m >= M_ALL) continue;
            int b = m / NTOK, n = m - b * NTOK;
#pragma unroll
            for (int nt = 0; nt < 4; nt++) {
                int j = j0 + wn + nt * 8 + t * 2;
#pragma unroll
                for (int c = 0; c < 2; c++) {
                    int jj = j + c;
                    float v = acc[mt][nt][h * 2 + c] + qkv_b[C_ + jj];
                    if (jj < C_) {
                        int hh = jj >> 6, d = jj & 63;
                        g_K[(((size_t)b * H_ + hh) * NTOK2 + n) * HD + d] =
                            __float2half_rn(v);
                    } else {
                        int j2 = jj - C_;
                        int hh = j2 >> 6, d = j2 & 63;
                        g_V[(((size_t)b * H_ + hh) * HD + d) * NTOK2 + n] =
                            __float2half_rn(v);
                    }
                }
            }
        }
    }
}

// ---------------------------------------------------------------------------
// Kernel 3: output projection. Grid (8, 33), 256 threads.
// ---------------------------------------------------------------------------
__global__ __launch_bounds__(256) void proj_kernel(
    const float* __restrict__ proj_w, const float* __restrict__ proj_b,
    float* __restrict__ out)
{
    extern __shared__ float sm_pj[];
    const int tid = threadIdx.x;
    const int m0 = blockIdx.y * 128, j0 = blockIdx.x * 128;
    const int wid = tid >> 5, lane = tid & 31;
    const int g = lane >> 2, t = lane & 3;
    const int wm = (wid >> 2) * 64, wn = (wid & 3) * 32;

    int arow = m0 + tid; if (arow >= M_ALL) arow = M_ALL - 1;
    int brow = j0 + (tid - 128);
    if (brow < 0) brow = 0;

    float acc[4][4][4];
#pragma unroll
    for (int a = 0; a < 4; a++)
#pragma unroll
        for (int b = 0; b < 4; b++)
#pragma unroll
            for (int c = 0; c < 4; c++) acc[a][b][c] = 0.f;

    wg_gemm_cvt(g_O, proj_w, arow, brow, sm_pj, acc, wm, wn, g, t);

#pragma unroll
    for (int mt = 0; mt < 4; mt++) {
#pragma unroll
        for (int h = 0; h < 2; h++) {
            int m = m0 + wm + mt * 16 + g + h * 8;
            if (m >= M_ALL) continue;
#pragma unroll
            for (int nt = 0; nt < 4; nt++) {
                int j = j0 + wn + nt * 8 + t * 2;
                float2 v = make_float2(acc[mt][nt][h * 2 + 0] + proj_b[j],
                                       acc[mt][nt][h * 2 + 1] + proj_b[j + 1]);
                *(float2*)(out + (size_t)m * C_ + j) = v;
            }
        }
    }
}

// ---------------------------------------------------------------------------
// Kernel 2: fused attention (R15 verbatim — passing at 5.5e-4).
// ---------------------------------------------------------------------------
__global__ __launch_bounds__(256, 2) void attn_fused_kernel(
    const float* __restrict__ addn, const float* __restrict__ rcs)
{
    extern __shared__ unsigned smu[];
    unsigned* Km = smu + KM_OFF;
    unsigned* Kn = smu + KN_OFF;
    unsigned* Vs = smu + VS_OFF;
    float*    Rb = (float*)(smu + RB_OFF);
    const int tid = threadIdx.x;
    const int bh = blockIdx.y;
    const int b = bh >> 4, hh = bh & 15;
    const int m0 = blockIdx.x * 128;
    const int wid = tid >> 5, lane = tid & 31;
    const int g = lane >> 2, t = lane & 3;
    const int r0 = wid * 16 + g;
    const int r1 = r0 + 8;
    const int gm0 = m0 + r0, gm1 = m0 + r1;
    const unsigned* Khw = (const unsigned*)g_K + (size_t)bh * NTOK2 * 32;
    const __half*   Vhh = g_V + (size_t)bh * HD * NTOK2;
    const float* Rbh = rcs + (size_t)bh * NTOK * NTOK;
    const float* ad0p = addn + (size_t)(gm0 < NTOK ? gm0 : 0) * NTOK;
    const float* ad1p = addn + (size_t)(gm1 < NTOK ? gm1 : 0) * NTOK;
    const uint32_t su = (uint32_t)__cvta_generic_to_shared(smu);
    const uint32_t kvbar = su + AT_BAR * 4;
    const uint32_t rcbar = kvbar + 8;

    if (tid == 0) { MBAR_INIT(kvbar, 1); MBAR_INIT(rcbar, 1); }

    {
        int row = tid >> 1, ch = (tid & 1) * 16;
        unsigned* dst = Km + row * LDKM + ch;
        if (m0 + row < NTOK) {
            const unsigned* src = Khw + (size_t)(m0 + row) * 32 + ch;
#pragma unroll
            for (int q = 0; q < 4; q++)
                *(uint4*)(dst + q * 4) = *(const uint4*)(src + q * 4);
        } else {
#pragma unroll
            for (int q = 0; q < 4; q++)
                *(uint4*)(dst + q * 4) = make_uint4(0u, 0u, 0u, 0u);
        }
    }

    float accS[8][4];
    float accP[8][4], accR[8][4];
#pragma unroll
    for (int nt = 0; nt < 8; nt++)
#pragma unroll
        for (int q = 0; q < 4; q++) { accP[nt][q] = 0.f; accR[nt][q] = 0.f; }
    float rs0 = 0.f, rs1 = 0.f;

    for (int it = 0; it < 17; it++) {
        const int n0 = it * 64;
        const bool last = (it == 16);
        __syncthreads();

        if (tid == 0) {
            MBAR_EXPECT(kvbar, 16384u);
            if (!last) MBAR_EXPECT(rcbar, 32768u);
        }
        __syncthreads();

        if (tid < 64) {
            bulkcp(su + (KN_OFF + tid * LDKN) * 4,
                   Khw + (size_t)(n0 + tid) * 32, 128u, kvbar);
        } else if (tid < 128) {
            int d = tid - 64;
            bulkcp(su + (VS_OFF + d * LDVS) * 4,
                   Vhh + (size_t)d * NTOK2 + n0, 128u, kvbar);
        } else if (!last) {
            int row = tid - 128;
            int mm = m0 + row; if (mm >= NTOK) mm = NTOK - 1;
            bulkcp(su + (RB_OFF + row * LDR) * 4,
                   Rbh + (size_t)mm * NTOK + n0, 256u, rcbar);
        }
        if (last) {
#pragma unroll
            for (int i = 0; i < 8; i++) {
                int c = tid + i * 256;
                int row = c >> 4, ch = (c & 15) * 4;
                int mm = m0 + row, nn = n0 + ch;
                int ok = (mm < NTOK) && (nn < NTOK);
                cpasync16(su + (RB_OFF + row * LDR + ch) * 4,
                          Rbh + (size_t)(ok ? mm : 0) * NTOK + (ok ? nn : 0),
                          ok ? 16 : 0);
            }
            asm volatile("cp.async.commit_group;");
        }

        MBAR_WAIT(kvbar, it & 1);

#pragma unroll
        for (int nt = 0; nt < 8; nt++)
#pragma unroll
            for (int q = 0; q < 4; q++) accS[nt][q] = 0.f;
#pragma unroll
        for (int kg = 0; kg < 4; kg++) {
            unsigned a0 = Km[r0 * LDKM + kg * 8 + t];
            unsigned a1 = Km[r1 * LDKM + kg * 8 + t];
            unsigned a2 = Km[r0 * LDKM + kg * 8 + t + 4];
            unsigned a3 = Km[r1 * LDKM + kg * 8 + t + 4];
#pragma unroll
            for (int nt = 0; nt < 8; nt++) {
                unsigned b0 = Kn[(nt * 8 + g) * LDKN + kg * 8 + t];
                unsigned b1 = Kn[(nt * 8 + g) * LDKN + kg * 8 + t + 4];
                mma_f16(accS[nt], a0, a1, a2, a3, b0, b1);
            }
        }

#pragma unroll
        for (int nt = 0; nt < 8; nt++) {
            int n = n0 + nt * 8 + 2 * t;
            if (n < NTOK) {
                float e0 = 0.f, e1 = 0.f, e2 = 0.f, e3 = 0.f;
                if (gm0 < NTOK) {
                    float2 a = *(const float2*)(ad0p + n);
                    e0 = __expf(SCALE * accS[nt][0] + a.x);
                    e1 = __expf(SCALE * accS[nt][1] + a.y);
                }
                if (gm1 < NTOK) {
                    float2 a = *(const float2*)(ad1p + n);
                    e2 = __expf(SCALE * accS[nt][2] + a.x);
                    e3 = __expf(SCALE * accS[nt][3] + a.y);
                }
                accS[nt][0] = e0; accS[nt][1] = e1;
                accS[nt][2] = e2; accS[nt][3] = e3;
                rs0 += e0 + e1; rs1 += e2 + e3;
            } else {
                accS[nt][0] = 0.f; accS[nt][1] = 0.f;
                accS[nt][2] = 0.f; accS[nt][3] = 0.f;
            }
        }

        if (!last) {
            MBAR_WAIT(rcbar, it & 1);
        } else {
            asm volatile("cp.async.wait_group 0;");
            __syncthreads();
        }

#pragma unroll
        for (int j = 0; j < 4; j++) {
            unsigned pa0 = f16x2(accS[2 * j][0],     accS[2 * j][1]);
            unsigned pa1 = f16x2(accS[2 * j][2],     accS[2 * j][3]);
            unsigned pa2 = f16x2(accS[2 * j + 1][0], accS[2 * j + 1][1]);
            unsigned pa3 = f16x2(accS[2 * j + 1][2], accS[2 * j + 1][3]);
            float2 q0 = *(const float2*)(Rb + r0 * LDR + j * 16 + 2 * t);
            float2 q1 = *(const float2*)(Rb + r1 * LDR + j * 16 + 2 * t);
            float2 q2 = *(const float2*)(Rb + r0 * LDR + j * 16 + 8 + 2 * t);
            float2 q3 = *(const float2*)(Rb + r1 * LDR + j * 16 + 8 + 2 * t);
            unsigned ra0 = f16x2(q0.x, q0.y);
            unsigned ra1 = f16x2(q1.x, q1.y);
            unsigned ra2 = f16x2(q2.x, q2.y);
            unsigned ra3 = f16x2(q3.x, q3.y);
#pragma unroll
            for (int nt = 0; nt < 8; nt++) {
                unsigned b0 = Vs[(nt * 8 + g) * LDVS + j * 8 + t];
                unsigned b1 = Vs[(nt * 8 + g) * LDVS + j * 8 + t + 4];
                mma_f16(accP[nt], pa0, pa1, pa2, pa3, b0, b1);
                mma_f16(accR[nt], ra0, ra1, ra2, ra3, b0, b1);
            }
        }
    }

    rs0 += __shfl_xor_sync(0xffffffffu, rs0, 1);
    rs0 += __shfl_xor_sync(0xffffffffu, rs0, 2);
    rs1 += __shfl_xor_sync(0xffffffffu, rs1, 1);
    rs1 += __shfl_xor_sync(0xffffffffu, rs1, 2);
    const float inv0 = W_SOFT / rs0, inv1 = W_SOFT / rs1;

    if (gm0 < NTOK) {
        float* op = g_O + ((size_t)b * NTOK + gm0) * C_ + hh * HD;
#pragma unroll
        for (int nt = 0; nt < 8; nt++) {
            int d = nt * 8 + 2 * t;
            float2 v = make_float2(accP[nt][0] * inv0 + W_RCS * accR[nt][0],
                                   accP[nt][1] * inv0 + W_RCS * accR[nt][1]);
            *(float2*)(op + d) = v;
        }
    }
    if (gm1 < NTOK) {
        float* op = g_O + ((size_t)b * NTOK + gm1) * C_ + hh * HD;
#pragma unroll
        for (int nt = 0; nt < 8; nt++) {
            int d = nt * 8 + 2 * t;
            float2 v = make_float2(accP[nt][2] * inv1 + W_RCS * accR[nt][2],
                                   accP[nt][3] * inv1 + W_RCS * accR[nt][3]);
            *(float2*)(op + d) = v;
        }
    }
}

// ---------------------------------------------------------------------------
extern "C" void kernel_launch(void* const* d_in, const int* in_sizes, int n_in,
                              void* d_out, int out_size)
{
    const float* x      = (const float*)d_in[0];
    const float* qkv_w  = (const float*)d_in[1];
    const float* qkv_b  = (const float*)d_in[2];
    const float* proj_w = (const float*)d_in[3];
    const float* proj_b = (const float*)d_in[4];
    const float* addn   = (const float*)d_in[5];
    const float* rcs    = (const float*)d_in[6];
    float* out = (float*)d_out;

    cudaFuncSetAttribute(kv_proj_kernel,
                         cudaFuncAttributeMaxDynamicSharedMemorySize,
                         GEMM_SMEM_BYTES);
    cudaFuncSetAttribute(proj_kernel,
                         cudaFuncAttributeMaxDynamicSharedMemorySize,
                         GEMM_SMEM_BYTES);
    cudaFuncSetAttribute(attn_fused_kernel,
                         cudaFuncAttributeMaxDynamicSharedMemorySize,
                         ATT_SMEM_BYTES);

    kv_proj_kernel<<<dim3(16, 33), 256, GEMM_SMEM_BYTES>>>(x, qkv_w, qkv_b);
    attn_fused_kernel<<<dim3(9, 64), 256, ATT_SMEM_BYTES>>>(addn, rcs);
    proj_kernel<<<dim3(8, 33), 256, GEMM_SMEM_BYTES>>>(proj_w, proj_b, out);
}

// round 17
// speedup vs baseline: 1.6279x; 1.2250x over previous
#include <cuda_runtime.h>
#include <cuda_fp16.h>
#include <cstdint>
#include <math.h>

// Problem constants
#define B_    4
#define NTOK  1032
#define NTOK2 1088
#define C_    1024
#define H_    16
#define HD    64
#define BH    64
#define M_ALL 4128
#define SCALE 0.125f
#define W_SOFT 0.8f
#define W_RCS  1.2f

// GEMM smem (words): 2 bufs x (A 128x36 + B 128x36); BK=64 fp16 per stage
#define GLD 36
#define GOPW (128 * GLD)                 // 4608 words per operand
#define GBUFW (2 * GOPW)                 // 9216 words per buffer
#define GBAR_W (2 * GBUFW)               // 18432
#define GEMM_SMEM_BYTES ((GBAR_W + 4) * 4)   // 73744 B
#define G_SBYTES 32768u                  // bytes per stage (A 16K + B 16K)

// attn smem (words) — R15/16 verbatim
#define LDKM 36
#define LDKN 36
#define LDVS 36
#define LDR  68
#define KM_OFF 0
#define KN_OFF (128 * LDKM)
#define VS_OFF (KN_OFF + 64 * LDKN)
#define RB_OFF (VS_OFF + 64 * LDVS)
#define AT_BAR (RB_OFF + 128 * LDR)
#define ATT_SMEM_BYTES ((AT_BAR + 8) * 4)

// Scratch (zero-initialized). Total ~41 MB.
__device__ __half g_Xh [(size_t)M_ALL * C_];      // x, fp16
__device__ __half g_Wh [(size_t)2 * C_ * C_];     // qkv_w rows [1024:3072), fp16
__device__ __half g_PWh[(size_t)C_ * C_];         // proj_w, fp16
__device__ __half g_K  [(size_t)BH * NTOK2 * HD]; // [bh][tok(1088)][d]
__device__ __half g_V  [(size_t)BH * HD * NTOK2]; // [bh][d][tok(1088)]
__device__ __half g_Oh [(size_t)M_ALL * C_];      // attn output, fp16

// ---------------------------------------------------------------------------
__device__ __forceinline__ unsigned f16x2(float lo, float hi) {
    unsigned r;
    asm("cvt.rn.f16x2.f32 %0, %1, %2;" : "=r"(r) : "f"(hi), "f"(lo));
    return r;
}
__device__ __forceinline__ void mma_f16(float* c, unsigned a0, unsigned a1,
                                        unsigned a2, unsigned a3,
                                        unsigned b0, unsigned b1) {
    asm volatile(
        "mma.sync.aligned.m16n8k16.row.col.f32.f16.f16.f32 "
        "{%0,%1,%2,%3},{%4,%5,%6,%7},{%8,%9},{%0,%1,%2,%3};"
        : "+f"(c[0]), "+f"(c[1]), "+f"(c[2]), "+f"(c[3])
        : "r"(a0), "r"(a1), "r"(a2), "r"(a3), "r"(b0), "r"(b1));
}
__device__ __forceinline__ void cpasync16(uint32_t dst, const void* src, int sbytes) {
    asm volatile("cp.async.cg.shared.global [%0], [%1], 16, %2;"
                 :: "r"(dst), "l"(src), "r"(sbytes));
}
__device__ __forceinline__ void bulkcp(uint32_t dst, const void* src,
                                       unsigned bytes, uint32_t bar) {
    asm volatile(
        "cp.async.bulk.shared::cluster.global.mbarrier::complete_tx::bytes "
        "[%0], [%1], %2, [%3];"
        :: "r"(dst), "l"(src), "r"(bytes), "r"(bar) : "memory");
}
#define MBAR_INIT(a, c) \
    asm volatile("mbarrier.init.shared.b64 [%0], %1;" :: "r"(a), "r"(c) : "memory")
#define MBAR_EXPECT(a, b) \
    asm volatile("mbarrier.arrive.expect_tx.shared.b64 _, [%0], %1;" \
                 :: "r"(a), "r"(b) : "memory")
#define MBAR_WAIT(a, ph) do { \
    uint32_t _m = (a), _p = (ph), _d; \
    asm volatile( \
        "{\n\t.reg .pred p;\n\t" \
        "mbarrier.try_wait.parity.acquire.cta.shared::cta.b64 p, [%1], %2;\n\t" \
        "selp.b32 %0, 1, 0, p;\n\t}" : "=r"(_d) : "r"(_m), "r"(_p) : "memory"); \
    if (!_d) { \
        asm volatile( \
            "{\n\t.reg .pred P1;\n\t" \
            "WL_%=:\n\t" \
            "mbarrier.try_wait.parity.acquire.cta.shared::cta.b64 P1, [%0], %1, 0x989680;\n\t" \
            "@P1 bra.uni WD_%=;\n\t" \
            "bra.uni WL_%=;\n\t" \
            "WD_%=:\n\t}" :: "r"(_m), "r"(_p) : "memory"); \
    } \
} while (0)

// ---------------------------------------------------------------------------
// Pre-pass: convert x / W_kv / proj_w to fp16 in one kernel. 8 floats/thread.
// Grid exactly covers N1+N2+N3 = 7,372,800 elements -> 3600 blocks.
// ---------------------------------------------------------------------------
__global__ __launch_bounds__(256) void cvt_all_kernel(
    const float* __restrict__ x, const float* __restrict__ qkv_w,
    const float* __restrict__ proj_w)
{
    const size_t N1 = (size_t)M_ALL * C_;
    const size_t N2 = (size_t)2 * C_ * C_;
    const size_t N3 = (size_t)C_ * C_;
    size_t i = ((size_t)blockIdx.x * 256 + threadIdx.x) * 8;
    const float* src;
    __half* dst;
    if (i < N1) {
        src = x + i; dst = g_Xh + i;
    } else if (i < N1 + N2) {
        size_t off = i - N1;
        src = qkv_w + (size_t)C_ * C_ + off; dst = g_Wh + off;
    } else if (i < N1 + N2 + N3) {
        size_t off = i - N1 - N2;
        src = proj_w + off; dst = g_PWh + off;
    } else {
        return;
    }
    float4 v0 = *(const float4*)src;
    float4 v1 = *(const float4*)(src + 4);
    uint4 o;
    o.x = f16x2(v0.x, v0.y); o.y = f16x2(v0.z, v0.w);
    o.z = f16x2(v1.x, v1.y); o.w = f16x2(v1.z, v1.w);
    *(uint4*)dst = o;
}

// ---------------------------------------------------------------------------
// GEMM mainloop: 128x128 tile, fp16 operands in global, K=1024 (16 stages of 64).
// Double-buffered bulk-copy fill; zero conversions in loop.
// ---------------------------------------------------------------------------
__device__ __forceinline__ void wg_gemm_h16(
    const __half* __restrict__ Abase, const __half* __restrict__ Bbase,
    int arow_idx, int brow_idx,
    unsigned* smem, float acc[4][4][4], int wm, int wn, int g, int t)
{
    const int tid = threadIdx.x;
    const uint32_t su = (uint32_t)__cvta_generic_to_shared(smem);
    const uint32_t bar0 = su + GBAR_W * 4;
    const uint32_t bar1 = bar0 + 8;

    if (tid == 0) { MBAR_INIT(bar0, 1); MBAR_INIT(bar1, 1); }
    __syncthreads();
    if (tid == 0) { MBAR_EXPECT(bar0, G_SBYTES); MBAR_EXPECT(bar1, G_SBYTES); }
    __syncthreads();

    const bool isA = (tid < 128);
    const __half* srcRow = isA ? (Abase + (size_t)arow_idx * C_)
                               : (Bbase + (size_t)brow_idx * C_);
    const int rowLocal = isA ? tid : (tid - 128);
    const uint32_t dstBase = su + ((isA ? 0 : GOPW) + rowLocal * GLD) * 4;

    // prologue: stages 0 and 1 (64 halves = 128B per row per stage)
    bulkcp(dstBase,             srcRow,      128u, bar0);
    bulkcp(dstBase + GBUFW * 4, srcRow + 64, 128u, bar1);

    for (int s = 0; s < 16; s++) {
        const int buf = s & 1;
        MBAR_WAIT(buf ? bar1 : bar0, (s >> 1) & 1);

        const unsigned* Ah = smem + buf * GBUFW;
        const unsigned* Bh = Ah + GOPW;
#pragma unroll
        for (int kg = 0; kg < 4; kg++) {
            unsigned a[4][4], bb[4][2];
#pragma unroll
            for (int mt = 0; mt < 4; mt++) {
                const unsigned* ap = Ah + (wm + mt * 16 + g) * GLD + kg * 8 + t;
                a[mt][0] = ap[0];
                a[mt][1] = ap[8 * GLD];
                a[mt][2] = ap[4];
                a[mt][3] = ap[8 * GLD + 4];
            }
#pragma unroll
            for (int nt = 0; nt < 4; nt++) {
                const unsigned* bp = Bh + (wn + nt * 8 + g) * GLD + kg * 8 + t;
                bb[nt][0] = bp[0];
                bb[nt][1] = bp[4];
            }
#pragma unroll
            for (int mt = 0; mt < 4; mt++)
#pragma unroll
                for (int nt = 0; nt < 4; nt++)
                    mma_f16(acc[mt][nt], a[mt][0], a[mt][1], a[mt][2], a[mt][3],
                            bb[nt][0], bb[nt][1]);
        }

        if (s + 2 < 16) {
            __syncthreads();   // all warps done reading buf
            if (tid == 0) MBAR_EXPECT(buf ? bar1 : bar0, G_SBYTES);
            __syncthreads();
            bulkcp(dstBase + buf * GBUFW * 4, srcRow + (s + 2) * 64, 128u,
                   buf ? bar1 : bar0);
        }
    }
}

// ---------------------------------------------------------------------------
// Kernel 1: K,V projection. Grid (16, 33), 256 threads.
// ---------------------------------------------------------------------------
__global__ __launch_bounds__(256) void kv_proj_kernel(
    const float* __restrict__ qkv_b)
{
    extern __shared__ unsigned sm_kv[];
    const int tid = threadIdx.x;
    const int m0 = blockIdx.y * 128, j0 = blockIdx.x * 128;
    const int wid = tid >> 5, lane = tid & 31;
    const int g = lane >> 2, t = lane & 3;
    const int wm = (wid >> 2) * 64, wn = (wid & 3) * 32;

    int arow = m0 + tid; if (arow >= M_ALL) arow = M_ALL - 1;
    int brow = j0 + (tid - 128);
    if (brow < 0) brow = 0;

    float acc[4][4][4];
#pragma unroll
    for (int a = 0; a < 4; a++)
#pragma unroll
        for (int b = 0; b < 4; b++)
#pragma unroll
            for (int c = 0; c < 4; c++) acc[a][b][c] = 0.f;

    wg_gemm_h16(g_Xh, g_Wh, arow, brow, sm_kv, acc, wm, wn, g, t);

#pragma unroll
    for (int mt = 0; mt < 4; mt++) {
#pragma unroll
        for (int h = 0; h < 2; h++) {
            int m = m0 + wm + mt * 16 + g + h * 8;
            if (m >= M_ALL) continue;
            int b = m / NTOK, n = m - b * NTOK;
#pragma unroll
            for (int nt = 0; nt < 4; nt++) {
                int j = j0 + wn + nt * 8 + t * 2;
#pragma unroll
                for (int c = 0; c < 2; c++) {
                    int jj = j + c;
                    float v = acc[mt][nt][h * 2 + c] + qkv_b[C_ + jj];
                    if (jj < C_) {
                        int hh = jj >> 6, d = jj & 63;
                        g_K[(((size_t)b * H_ + hh) * NTOK2 + n) * HD + d] =
                            __float2half_rn(v);
                    } else {
                        int j2 = jj - C_;
                        int hh = j2 >> 6, d = j2 & 63;
                        g_V[(((size_t)b * H_ + hh) * HD + d) * NTOK2 + n] =
                            __float2half_rn(v);
                    }
                }
            }
        }
    }
}

// ---------------------------------------------------------------------------
// Kernel 3: output projection. Grid (8, 33), 256 threads. A = g_Oh (fp16).
// ---------------------------------------------------------------------------
__global__ __launch_bounds__(256) void proj_kernel(
    const float* __restrict__ proj_b, float* __restrict__ out)
{
    extern __shared__ unsigned sm_pj[];
    const int tid = threadIdx.x;
    const int m0 = blockIdx.y * 128, j0 = blockIdx.x * 128;
    const int wid = tid >> 5, lane = tid & 31;
    const int g = lane >> 2, t = lane & 3;
    const int wm = (wid >> 2) * 64, wn = (wid & 3) * 32;

    int arow = m0 + tid; if (arow >= M_ALL) arow = M_ALL - 1;
    int brow = j0 + (tid - 128);
    if (brow < 0) brow = 0;

    float acc[4][4][4];
#pragma unroll
    for (int a = 0; a < 4; a++)
#pragma unroll
        for (int b = 0; b < 4; b++)
#pragma unroll
            for (int c = 0; c < 4; c++) acc[a][b][c] = 0.f;

    wg_gemm_h16(g_Oh, g_PWh, arow, brow, sm_pj, acc, wm, wn, g, t);

#pragma unroll
    for (int mt = 0; mt < 4; mt++) {
#pragma unroll
        for (int h = 0; h < 2; h++) {
            int m = m0 + wm + mt * 16 + g + h * 8;
            if (m >= M_ALL) continue;
#pragma unroll
            for (int nt = 0; nt < 4; nt++) {
                int j = j0 + wn + nt * 8 + t * 2;
                float2 v = make_float2(acc[mt][nt][h * 2 + 0] + proj_b[j],
                                       acc[mt][nt][h * 2 + 1] + proj_b[j + 1]);
                *(float2*)(out + (size_t)m * C_ + j) = v;
            }
        }
    }
}

// ---------------------------------------------------------------------------
// Kernel 2: fused attention (R16 verbatim; epilogue stores fp16 to g_Oh).
// ---------------------------------------------------------------------------
__global__ __launch_bounds__(256, 2) void attn_fused_kernel(
    const float* __restrict__ addn, const float* __restrict__ rcs)
{
    extern __shared__ unsigned smu[];
    unsigned* Km = smu + KM_OFF;
    unsigned* Kn = smu + KN_OFF;
    unsigned* Vs = smu + VS_OFF;
    float*    Rb = (float*)(smu + RB_OFF);
    const int tid = threadIdx.x;
    const int bh = blockIdx.y;
    const int b = bh >> 4, hh = bh & 15;
    const int m0 = blockIdx.x * 128;
    const int wid = tid >> 5, lane = tid & 31;
    const int g = lane >> 2, t = lane & 3;
    const int r0 = wid * 16 + g;
    const int r1 = r0 + 8;
    const int gm0 = m0 + r0, gm1 = m0 + r1;
    const unsigned* Khw = (const unsigned*)g_K + (size_t)bh * NTOK2 * 32;
    const __half*   Vhh = g_V + (size_t)bh * HD * NTOK2;
    const float* Rbh = rcs + (size_t)bh * NTOK * NTOK;
    const float* ad0p = addn + (size_t)(gm0 < NTOK ? gm0 : 0) * NTOK;
    const float* ad1p = addn + (size_t)(gm1 < NTOK ? gm1 : 0) * NTOK;
    const uint32_t su = (uint32_t)__cvta_generic_to_shared(smu);
    const uint32_t kvbar = su + AT_BAR * 4;
    const uint32_t rcbar = kvbar + 8;

    if (tid == 0) { MBAR_INIT(kvbar, 1); MBAR_INIT(rcbar, 1); }

    {
        int row = tid >> 1, ch = (tid & 1) * 16;
        unsigned* dst = Km + row * LDKM + ch;
        if (m0 + row < NTOK) {
            const unsigned* src = Khw + (size_t)(m0 + row) * 32 + ch;
#pragma unroll
            for (int q = 0; q < 4; q++)
                *(uint4*)(dst + q * 4) = *(const uint4*)(src + q * 4);
        } else {
#pragma unroll
            for (int q = 0; q < 4; q++)
                *(uint4*)(dst + q * 4) = make_uint4(0u, 0u, 0u, 0u);
        }
    }

    float accS[8][4];
    float accP[8][4], accR[8][4];
#pragma unroll
    for (int nt = 0; nt < 8; nt++)
#pragma unroll
        for (int q = 0; q < 4; q++) { accP[nt][q] = 0.f; accR[nt][q] = 0.f; }
    float rs0 = 0.f, rs1 = 0.f;

    for (int it = 0; it < 17; it++) {
        const int n0 = it * 64;
        const bool last = (it == 16);
        __syncthreads();

        if (tid == 0) {
            MBAR_EXPECT(kvbar, 16384u);
            if (!last) MBAR_EXPECT(rcbar, 32768u);
        }
        __syncthreads();

        if (tid < 64) {
            bulkcp(su + (KN_OFF + tid * LDKN) * 4,
                   Khw + (size_t)(n0 + tid) * 32, 128u, kvbar);
        } else if (tid < 128) {
            int d = tid - 64;
            bulkcp(su + (VS_OFF + d * LDVS) * 4,
                   Vhh + (size_t)d * NTOK2 + n0, 128u, kvbar);
        } else if (!last) {
            int row = tid - 128;
            int mm = m0 + row; if (mm >= NTOK) mm = NTOK - 1;
            bulkcp(su + (RB_OFF + row * LDR) * 4,
                   Rbh + (size_t)mm * NTOK + n0, 256u, rcbar);
        }
        if (last) {
#pragma unroll
            for (int i = 0; i < 8; i++) {
                int c = tid + i * 256;
                int row = c >> 4, ch = (c & 15) * 4;
                int mm = m0 + row, nn = n0 + ch;
                int ok = (mm < NTOK) && (nn < NTOK);
                cpasync16(su + (RB_OFF + row * LDR + ch) * 4,
                          Rbh + (size_t)(ok ? mm : 0) * NTOK + (ok ? nn : 0),
                          ok ? 16 : 0);
            }
            asm volatile("cp.async.commit_group;");
        }

        MBAR_WAIT(kvbar, it & 1);

#pragma unroll
        for (int nt = 0; nt < 8; nt++)
#pragma unroll
            for (int q = 0; q < 4; q++) accS[nt][q] = 0.f;
#pragma unroll
        for (int kg = 0; kg < 4; kg++) {
            unsigned a0 = Km[r0 * LDKM + kg * 8 + t];
            unsigned a1 = Km[r1 * LDKM + kg * 8 + t];
            unsigned a2 = Km[r0 * LDKM + kg * 8 + t + 4];
            unsigned a3 = Km[r1 * LDKM + kg * 8 + t + 4];
#pragma unroll
            for (int nt = 0; nt < 8; nt++) {
                unsigned b0 = Kn[(nt * 8 + g) * LDKN + kg * 8 + t];
                unsigned b1 = Kn[(nt * 8 + g) * LDKN + kg * 8 + t + 4];
                mma_f16(accS[nt], a0, a1, a2, a3, b0, b1);
            }
        }

#pragma unroll
        for (int nt = 0; nt < 8; nt++) {
            int n = n0 + nt * 8 + 2 * t;
            if (n < NTOK) {
                float e0 = 0.f, e1 = 0.f, e2 = 0.f, e3 = 0.f;
                if (gm0 < NTOK) {
                    float2 a = *(const float2*)(ad0p + n);
                    e0 = __expf(SCALE * accS[nt][0] + a.x);
                    e1 = __expf(SCALE * accS[nt][1] + a.y);
                }
                if (gm1 < NTOK) {
                    float2 a = *(const float2*)(ad1p + n);
                    e2 = __expf(SCALE * accS[nt][2] + a.x);
                    e3 = __expf(SCALE * accS[nt][3] + a.y);
                }
                accS[nt][0] = e0; accS[nt][1] = e1;
                accS[nt][2] = e2; accS[nt][3] = e3;
                rs0 += e0 + e1; rs1 += e2 + e3;
            } else {
                accS[nt][0] = 0.f; accS[nt][1] = 0.f;
                accS[nt][2] = 0.f; accS[nt][3] = 0.f;
            }
        }

        if (!last) {
            MBAR_WAIT(rcbar, it & 1);
        } else {
            asm volatile("cp.async.wait_group 0;");
            __syncthreads();
        }

#pragma unroll
        for (int j = 0; j < 4; j++) {
            unsigned pa0 = f16x2(accS[2 * j][0],     accS[2 * j][1]);
            unsigned pa1 = f16x2(accS[2 * j][2],     accS[2 * j][3]);
            unsigned pa2 = f16x2(accS[2 * j + 1][0], accS[2 * j + 1][1]);
            unsigned pa3 = f16x2(accS[2 * j + 1][2], accS[2 * j + 1][3]);
            float2 q0 = *(const float2*)(Rb + r0 * LDR + j * 16 + 2 * t);
            float2 q1 = *(const float2*)(Rb + r1 * LDR + j * 16 + 2 * t);
            float2 q2 = *(const float2*)(Rb + r0 * LDR + j * 16 + 8 + 2 * t);
            float2 q3 = *(const float2*)(Rb + r1 * LDR + j * 16 + 8 + 2 * t);
            unsigned ra0 = f16x2(q0.x, q0.y);
            unsigned ra1 = f16x2(q1.x, q1.y);
            unsigned ra2 = f16x2(q2.x, q2.y);
            unsigned ra3 = f16x2(q3.x, q3.y);
#pragma unroll
            for (int nt = 0; nt < 8; nt++) {
                unsigned b0 = Vs[(nt * 8 + g) * LDVS + j * 8 + t];
                unsigned b1 = Vs[(nt * 8 + g) * LDVS + j * 8 + t + 4];
                mma_f16(accP[nt], pa0, pa1, pa2, pa3, b0, b1);
                mma_f16(accR[nt], ra0, ra1, ra2, ra3, b0, b1);
            }
        }
    }

    rs0 += __shfl_xor_sync(0xffffffffu, rs0, 1);
    rs0 += __shfl_xor_sync(0xffffffffu, rs0, 2);
    rs1 += __shfl_xor_sync(0xffffffffu, rs1, 1);
    rs1 += __shfl_xor_sync(0xffffffffu, rs1, 2);
    const float inv0 = W_SOFT / rs0, inv1 = W_SOFT / rs1;

    if (gm0 < NTOK) {
        __half* op = g_Oh + ((size_t)b * NTOK + gm0) * C_ + hh * HD;
#pragma unroll
        for (int nt = 0; nt < 8; nt++) {
            int d = nt * 8 + 2 * t;
            *(unsigned*)(op + d) =
                f16x2(accP[nt][0] * inv0 + W_RCS * accR[nt][0],
                      accP[nt][1] * inv0 + W_RCS * accR[nt][1]);
        }
    }
    if (gm1 < NTOK) {
        __half* op = g_Oh + ((size_t)b * NTOK + gm1) * C_ + hh * HD;
#pragma unroll
        for (int nt = 0; nt < 8; nt++) {
            int d = nt * 8 + 2 * t;
            *(unsigned*)(op + d) =
                f16x2(accP[nt][2] * inv1 + W_RCS * accR[nt][2],
                      accP[nt][3] * inv1 + W_RCS * accR[nt][3]);
        }
    }
}

// ---------------------------------------------------------------------------
extern "C" void kernel_launch(void* const* d_in, const int* in_sizes, int n_in,
                              void* d_out, int out_size)
{
    const float* x      = (const float*)d_in[0];
    const float* qkv_w  = (const float*)d_in[1];
    const float* qkv_b  = (const float*)d_in[2];
    const float* proj_w = (const float*)d_in[3];
    const float* proj_b = (const float*)d_in[4];
    const float* addn   = (const float*)d_in[5];
    const float* rcs    = (const float*)d_in[6];
    float* out = (float*)d_out;

    cudaFuncSetAttribute(kv_proj_kernel,
                         cudaFuncAttributeMaxDynamicSharedMemorySize,
                         GEMM_SMEM_BYTES);
    cudaFuncSetAttribute(proj_kernel,
                         cudaFuncAttributeMaxDynamicSharedMemorySize,
                         GEMM_SMEM_BYTES);
    cudaFuncSetAttribute(attn_fused_kernel,
                         cudaFuncAttributeMaxDynamicSharedMemorySize,
                         ATT_SMEM_BYTES);

    cvt_all_kernel<<<3600, 256>>>(x, qkv_w, proj_w);
    kv_proj_kernel<<<dim3(16, 33), 256, GEMM_SMEM_BYTES>>>(qkv_b);
    attn_fused_kernel<<<dim3(9, 64), 256, ATT_SMEM_BYTES>>>(addn, rcs);
    proj_kernel<<<dim3(8, 33), 256, GEMM_SMEM_BYTES>>>(proj_b, out);
}